// round 3
// baseline (speedup 1.0000x reference)
#include <cuda_runtime.h>
#include <cuda_bf16.h>
#include <math.h>
#include <math_constants.h>

// Problem constants
#define BB 32
#define SS 512
#define DD 256
#define HH 8
#define DHH 32
// rows = B*S = 16384
#define NROWS (BB*SS)

// Scratch (allocation is banned -> __device__ globals)
__device__ float g_qkv[(size_t)NROWS * 768];   // [row][0:256)=q(h,e), [256:512)=k, [512:768)=v
__device__ float g_tmp[(size_t)NROWS * 256];   // avg @ v result

// ---------------------------------------------------------------------------
// SGEMM  C[M,N] = A[M,K] * B[N,K]^T  (+bias[n])    (both A and B K-contiguous)
// 64x64 tile, KT=16, 256 threads, 4x4 microtile.
// ---------------------------------------------------------------------------
__global__ __launch_bounds__(256) void gemm_tn(
    const float* __restrict__ A, const float* __restrict__ B,
    const float* __restrict__ bias, float* __restrict__ C,
    int K, int lda, int ldb, int ldc)
{
    __shared__ __align__(16) float As[16][68];
    __shared__ __align__(16) float Bs[16][68];
    const int m0 = blockIdx.y * 64;
    const int n0 = blockIdx.x * 64;
    const int tid = threadIdx.x;
    const int tx = tid & 15, ty = tid >> 4;
    const int lm = tid >> 2, lk4 = (tid & 3) * 4;

    float c[4][4];
#pragma unroll
    for (int i = 0; i < 4; ++i)
#pragma unroll
        for (int j = 0; j < 4; ++j) c[i][j] = 0.f;

    for (int k0 = 0; k0 < K; k0 += 16) {
        float4 av = *(const float4*)(A + (size_t)(m0 + lm) * lda + k0 + lk4);
        float4 bv = *(const float4*)(B + (size_t)(n0 + lm) * ldb + k0 + lk4);
        As[lk4 + 0][lm] = av.x; As[lk4 + 1][lm] = av.y;
        As[lk4 + 2][lm] = av.z; As[lk4 + 3][lm] = av.w;
        Bs[lk4 + 0][lm] = bv.x; Bs[lk4 + 1][lm] = bv.y;
        Bs[lk4 + 2][lm] = bv.z; Bs[lk4 + 3][lm] = bv.w;
        __syncthreads();
#pragma unroll
        for (int kk = 0; kk < 16; ++kk) {
            float4 a4 = *(const float4*)&As[kk][ty * 4];
            float4 b4 = *(const float4*)&Bs[kk][tx * 4];
            float a[4] = {a4.x, a4.y, a4.z, a4.w};
            float bb[4] = {b4.x, b4.y, b4.z, b4.w};
#pragma unroll
            for (int i = 0; i < 4; ++i)
#pragma unroll
                for (int j = 0; j < 4; ++j) c[i][j] = fmaf(a[i], bb[j], c[i][j]);
        }
        __syncthreads();
    }
#pragma unroll
    for (int i = 0; i < 4; ++i) {
        float4 o;
        int n = n0 + tx * 4;
        float b0 = bias ? bias[n + 0] : 0.f;
        float b1 = bias ? bias[n + 1] : 0.f;
        float b2 = bias ? bias[n + 2] : 0.f;
        float b3 = bias ? bias[n + 3] : 0.f;
        o.x = c[i][0] + b0; o.y = c[i][1] + b1; o.z = c[i][2] + b2; o.w = c[i][3] + b3;
        *(float4*)(C + (size_t)(m0 + ty * 4 + i) * ldc + n) = o;
    }
}

// ---------------------------------------------------------------------------
// Batched SGEMM  C = A[M,K] * B[K,N]   (A K-contig rows, B N-contig rows)
// ---------------------------------------------------------------------------
__global__ __launch_bounds__(256) void gemm_nn_batched(
    const float* __restrict__ Ab, const float* __restrict__ Bb,
    float* __restrict__ Cb,
    int K, int lda, int ldb, int ldc,
    size_t strideA, size_t strideB, size_t strideC)
{
    const float* A = Ab + (size_t)blockIdx.z * strideA;
    const float* B = Bb + (size_t)blockIdx.z * strideB;
    float* C = Cb + (size_t)blockIdx.z * strideC;

    __shared__ __align__(16) float As[16][68];
    __shared__ __align__(16) float Bs[16][68];
    const int m0 = blockIdx.y * 64;
    const int n0 = blockIdx.x * 64;
    const int tid = threadIdx.x;
    const int tx = tid & 15, ty = tid >> 4;
    const int lm = tid >> 2, lk4 = (tid & 3) * 4;    // A loader
    const int lkr = tid >> 4, lnq = (tid & 15) * 4;  // B loader

    float c[4][4];
#pragma unroll
    for (int i = 0; i < 4; ++i)
#pragma unroll
        for (int j = 0; j < 4; ++j) c[i][j] = 0.f;

    for (int k0 = 0; k0 < K; k0 += 16) {
        float4 av = *(const float4*)(A + (size_t)(m0 + lm) * lda + k0 + lk4);
        float4 bv = *(const float4*)(B + (size_t)(k0 + lkr) * ldb + n0 + lnq);
        As[lk4 + 0][lm] = av.x; As[lk4 + 1][lm] = av.y;
        As[lk4 + 2][lm] = av.z; As[lk4 + 3][lm] = av.w;
        *(float4*)&Bs[lkr][lnq] = bv;
        __syncthreads();
#pragma unroll
        for (int kk = 0; kk < 16; ++kk) {
            float4 a4 = *(const float4*)&As[kk][ty * 4];
            float4 b4 = *(const float4*)&Bs[kk][tx * 4];
            float a[4] = {a4.x, a4.y, a4.z, a4.w};
            float bb[4] = {b4.x, b4.y, b4.z, b4.w};
#pragma unroll
            for (int i = 0; i < 4; ++i)
#pragma unroll
                for (int j = 0; j < 4; ++j) c[i][j] = fmaf(a[i], bb[j], c[i][j]);
        }
        __syncthreads();
    }
#pragma unroll
    for (int i = 0; i < 4; ++i) {
        float4 o = make_float4(c[i][0], c[i][1], c[i][2], c[i][3]);
        *(float4*)(C + (size_t)(m0 + ty * 4 + i) * ldc + n0 + tx * 4) = o;
    }
}

// ---------------------------------------------------------------------------
// Attention scores + exact sparsemax (Michelot) + head-average.
// One warp per query row s; 16 rows (16 warps, 512 threads) per block.
// K tile for (batch, head) staged in shared memory (512 x 32, pad 33).
// z and the head-averaged attention row live in registers (16 per lane).
// Writes avg_attention [B,S,S] directly.
// ---------------------------------------------------------------------------
#define ATTN_SMEM_BYTES ((512 * 33 + 512) * 4)

__global__ __launch_bounds__(512) void attn_sparsemax_kernel(
    const float* __restrict__ qkv, float* __restrict__ avg)
{
    extern __shared__ float smem[];
    float* Ksh = smem;               // 512*33
    float* Qsh = smem + 512 * 33;    // 16*32

    const int tid = threadIdx.x;
    const int w = tid >> 5, lane = tid & 31;
    const int row0 = blockIdx.x * 16;
    const int b = row0 >> 9;
    const int s0 = row0 & 511;
    const int s = s0 + w;

    float acc[16];
#pragma unroll
    for (int i = 0; i < 16; ++i) acc[i] = 0.f;

    for (int h = 0; h < HH; ++h) {
        // stage K_h for this batch: k row (t) = qkv[(b*512+t)*768 + 256 + h*32 + e]
#pragma unroll
        for (int j = 0; j < 8; ++j) {
            int idx4 = tid + j * 512;          // 4096 float4s
            int t = idx4 >> 3;
            int c4 = (idx4 & 7) * 4;
            float4 v = *(const float4*)(qkv + (size_t)(b * 512 + t) * 768 + 256 + h * 32 + c4);
            float* d = &Ksh[t * 33 + c4];
            d[0] = v.x; d[1] = v.y; d[2] = v.z; d[3] = v.w;
        }
        {
            int r = tid >> 5, e = tid & 31;
            Qsh[r * 32 + e] = qkv[(size_t)(b * 512 + s0 + r) * 768 + h * 32 + e];
        }
        __syncthreads();

        float q[32];
#pragma unroll
        for (int e = 0; e < 32; ++e) q[e] = Qsh[w * 32 + e];

        float z[16];
#pragma unroll
        for (int i = 0; i < 16; ++i) {
            int t = lane + i * 32;
            const float* kr = &Ksh[t * 33];
            float zz = 0.f;
#pragma unroll
            for (int e = 0; e < 32; ++e) zz = fmaf(q[e], kr[e], zz);
            z[i] = zz * 0.17677669529663687f;   // 1/sqrt(32)
            if (t == s) z[i] = -CUDART_INF_F;   // diagonal mask
        }

        // Michelot's exact simplex projection: tau <- (sum_{z>tau} z - 1)/count
        float tau = -CUDART_INF_F;
        int prevc = -1;
        for (int it = 0; it < 128; ++it) {
            float sa = 0.f;
            int ca = 0;
#pragma unroll
            for (int i = 0; i < 16; ++i) {
                if (z[i] > tau) { sa += z[i]; ca++; }
            }
#pragma unroll
            for (int o = 16; o; o >>= 1) {
                sa += __shfl_xor_sync(0xffffffffu, sa, o);
                ca += __shfl_xor_sync(0xffffffffu, ca, o);
            }
            if (ca == prevc || ca == 0) break;
            prevc = ca;
            tau = (sa - 1.0f) / (float)ca;
        }

#pragma unroll
        for (int i = 0; i < 16; ++i)
            acc[i] += fmaxf(z[i] - tau, 0.f) * 0.125f;   // /H
        __syncthreads();
    }

    float* dst = avg + (size_t)(b * 512 + s) * 512;
#pragma unroll
    for (int i = 0; i < 16; ++i) dst[lane + i * 32] = acc[i];
}

// ---------------------------------------------------------------------------
extern "C" void kernel_launch(void* const* d_in, const int* in_sizes, int n_in,
                              void* d_out, int out_size)
{
    const float* x  = (const float*)d_in[0];  // [32,512,256]
    const float* Wq = (const float*)d_in[1];  // [8,32,256]
    const float* bq = (const float*)d_in[2];  // [8,32]
    const float* Wk = (const float*)d_in[3];
    const float* bk = (const float*)d_in[4];
    const float* Wv = (const float*)d_in[5];  // [256,256]
    const float* bv = (const float*)d_in[6];
    const float* Wo = (const float*)d_in[7];
    const float* bo = (const float*)d_in[8];

    float* out = (float*)d_out;                        // [32,512,256]
    float* avg = out + (size_t)NROWS * DD;             // [32,512,512]

    float* qkv = nullptr;
    float* tmp = nullptr;
    cudaGetSymbolAddress((void**)&qkv, g_qkv);
    cudaGetSymbolAddress((void**)&tmp, g_tmp);

    cudaFuncSetAttribute(attn_sparsemax_kernel,
                         cudaFuncAttributeMaxDynamicSharedMemorySize, ATTN_SMEM_BYTES);

    dim3 blk(256);

    // 1) projections: qkv[row][0:256)=q, [256:512)=k, [512:768)=v
    {
        dim3 grid(256 / 64, NROWS / 64);
        gemm_tn<<<grid, blk>>>(x, Wq, bq, qkv + 0,   DD, DD, DD, 768);
        gemm_tn<<<grid, blk>>>(x, Wk, bk, qkv + 256, DD, DD, DD, 768);
        gemm_tn<<<grid, blk>>>(x, Wv, bv, qkv + 512, DD, DD, DD, 768);
    }

    // 2) scores + sparsemax + head average -> avg_attention (in d_out)
    attn_sparsemax_kernel<<<NROWS / 16, 512, ATTN_SMEM_BYTES>>>(qkv, avg);

    // 3) tmp[b] = avg[b] @ v[b]   (M=512, N=256, K=512; v strided inside qkv)
    {
        dim3 grid(256 / 64, 512 / 64, BB);
        gemm_nn_batched<<<grid, blk>>>(avg, qkv + 512, tmp,
                                       SS, SS, 768, DD,
                                       (size_t)SS * SS, (size_t)SS * 768, (size_t)SS * DD);
    }

    // 4) out = tmp @ Wo^T + bo
    {
        dim3 grid(256 / 64, NROWS / 64);
        gemm_tn<<<grid, blk>>>(tmp, Wo, bo, out, DD, DD, DD, DD);
    }
}

// round 4
// speedup vs baseline: 1.9027x; 1.9027x over previous
#include <cuda_runtime.h>
#include <cuda_bf16.h>
#include <math.h>
#include <math_constants.h>

// Problem constants
#define BB 32
#define SS 512
#define DD 256
#define HH 8
#define DHH 32
#define NROWS (BB*SS)

// Scratch (allocation is banned -> __device__ globals)
__device__ float g_qkv[(size_t)NROWS * 768];   // [row][0:256)=q(h,e), [256:512)=k, [512:768)=v
__device__ float g_tmp[(size_t)NROWS * 256];   // avg @ v result

// ---------------------------------------------------------------------------
// SGEMM  C[M,N] = A[M,K] * B[N,K]^T  (+bias[n])
// ---------------------------------------------------------------------------
__global__ __launch_bounds__(256) void gemm_tn(
    const float* __restrict__ A, const float* __restrict__ B,
    const float* __restrict__ bias, float* __restrict__ C,
    int K, int lda, int ldb, int ldc)
{
    __shared__ __align__(16) float As[16][68];
    __shared__ __align__(16) float Bs[16][68];
    const int m0 = blockIdx.y * 64;
    const int n0 = blockIdx.x * 64;
    const int tid = threadIdx.x;
    const int tx = tid & 15, ty = tid >> 4;
    const int lm = tid >> 2, lk4 = (tid & 3) * 4;

    float c[4][4];
#pragma unroll
    for (int i = 0; i < 4; ++i)
#pragma unroll
        for (int j = 0; j < 4; ++j) c[i][j] = 0.f;

    for (int k0 = 0; k0 < K; k0 += 16) {
        float4 av = *(const float4*)(A + (size_t)(m0 + lm) * lda + k0 + lk4);
        float4 bv = *(const float4*)(B + (size_t)(n0 + lm) * ldb + k0 + lk4);
        As[lk4 + 0][lm] = av.x; As[lk4 + 1][lm] = av.y;
        As[lk4 + 2][lm] = av.z; As[lk4 + 3][lm] = av.w;
        Bs[lk4 + 0][lm] = bv.x; Bs[lk4 + 1][lm] = bv.y;
        Bs[lk4 + 2][lm] = bv.z; Bs[lk4 + 3][lm] = bv.w;
        __syncthreads();
#pragma unroll
        for (int kk = 0; kk < 16; ++kk) {
            float4 a4 = *(const float4*)&As[kk][ty * 4];
            float4 b4 = *(const float4*)&Bs[kk][tx * 4];
            float a[4] = {a4.x, a4.y, a4.z, a4.w};
            float bb[4] = {b4.x, b4.y, b4.z, b4.w};
#pragma unroll
            for (int i = 0; i < 4; ++i)
#pragma unroll
                for (int j = 0; j < 4; ++j) c[i][j] = fmaf(a[i], bb[j], c[i][j]);
        }
        __syncthreads();
    }
#pragma unroll
    for (int i = 0; i < 4; ++i) {
        float4 o;
        int n = n0 + tx * 4;
        float b0 = bias ? bias[n + 0] : 0.f;
        float b1 = bias ? bias[n + 1] : 0.f;
        float b2 = bias ? bias[n + 2] : 0.f;
        float b3 = bias ? bias[n + 3] : 0.f;
        o.x = c[i][0] + b0; o.y = c[i][1] + b1; o.z = c[i][2] + b2; o.w = c[i][3] + b3;
        *(float4*)(C + (size_t)(m0 + ty * 4 + i) * ldc + n) = o;
    }
}

// ---------------------------------------------------------------------------
// Batched SGEMM  C = A[M,K] * B[K,N]
// ---------------------------------------------------------------------------
__global__ __launch_bounds__(256) void gemm_nn_batched(
    const float* __restrict__ Ab, const float* __restrict__ Bb,
    float* __restrict__ Cb,
    int K, int lda, int ldb, int ldc,
    size_t strideA, size_t strideB, size_t strideC)
{
    const float* A = Ab + (size_t)blockIdx.z * strideA;
    const float* B = Bb + (size_t)blockIdx.z * strideB;
    float* C = Cb + (size_t)blockIdx.z * strideC;

    __shared__ __align__(16) float As[16][68];
    __shared__ __align__(16) float Bs[16][68];
    const int m0 = blockIdx.y * 64;
    const int n0 = blockIdx.x * 64;
    const int tid = threadIdx.x;
    const int tx = tid & 15, ty = tid >> 4;
    const int lm = tid >> 2, lk4 = (tid & 3) * 4;
    const int lkr = tid >> 4, lnq = (tid & 15) * 4;

    float c[4][4];
#pragma unroll
    for (int i = 0; i < 4; ++i)
#pragma unroll
        for (int j = 0; j < 4; ++j) c[i][j] = 0.f;

    for (int k0 = 0; k0 < K; k0 += 16) {
        float4 av = *(const float4*)(A + (size_t)(m0 + lm) * lda + k0 + lk4);
        float4 bv = *(const float4*)(B + (size_t)(k0 + lkr) * ldb + n0 + lnq);
        As[lk4 + 0][lm] = av.x; As[lk4 + 1][lm] = av.y;
        As[lk4 + 2][lm] = av.z; As[lk4 + 3][lm] = av.w;
        *(float4*)&Bs[lkr][lnq] = bv;
        __syncthreads();
#pragma unroll
        for (int kk = 0; kk < 16; ++kk) {
            float4 a4 = *(const float4*)&As[kk][ty * 4];
            float4 b4 = *(const float4*)&Bs[kk][tx * 4];
            float a[4] = {a4.x, a4.y, a4.z, a4.w};
            float bb[4] = {b4.x, b4.y, b4.z, b4.w};
#pragma unroll
            for (int i = 0; i < 4; ++i)
#pragma unroll
                for (int j = 0; j < 4; ++j) c[i][j] = fmaf(a[i], bb[j], c[i][j]);
        }
        __syncthreads();
    }
#pragma unroll
    for (int i = 0; i < 4; ++i) {
        float4 o = make_float4(c[i][0], c[i][1], c[i][2], c[i][3]);
        *(float4*)(C + (size_t)(m0 + ty * 4 + i) * ldc + n0 + tx * 4) = o;
    }
}

// ---------------------------------------------------------------------------
// Attention v2: scores as 4x4-microtile mini-GEMM on a TRANSPOSED K tile
// (Ks[e][t], conflict-free), scores tile in smem, then warp-per-query
// exact sparsemax (Michelot) with head-averaged rows in registers.
//
// Block: 512 threads, 16 query rows, loops over 8 heads.
// Smem: Ks 32x528 (67.6KB) + Qs 32x20 (2.6KB) + Ssc 16x520 (33.3KB) ~ 101KB
// -> 2 blocks/SM (occ 50%).
// ---------------------------------------------------------------------------
#define KS_STRIDE 528           // 512 + 16 pad (float4 row stride 132 -> 528B%128B=16B: conflict-free e-major stores)
#define QS_STRIDE 20
#define SS_STRIDE 520
#define ATTN_SMEM_FLOATS (32*KS_STRIDE + 32*QS_STRIDE + 16*SS_STRIDE)
#define ATTN_SMEM_BYTES (ATTN_SMEM_FLOATS * 4)

__global__ __launch_bounds__(512, 2) void attn_sparsemax_kernel(
    const float* __restrict__ qkv, float* __restrict__ avg)
{
    extern __shared__ __align__(16) float smem[];
    float* Ks  = smem;                                  // [32][KS_STRIDE] e-major
    float* Qs  = smem + 32 * KS_STRIDE;                 // [32][QS_STRIDE] e-major
    float* Ssc = Qs + 32 * QS_STRIDE;                   // [16][SS_STRIDE]

    const int tid  = threadIdx.x;
    const int w    = tid >> 5, lane = tid & 31;
    const int b    = blockIdx.x >> 5;
    const int s0   = (blockIdx.x & 31) << 4;
    const int s    = s0 + w;                            // this warp's query (sparsemax phase)
    const int tx   = tid & 127;                         // key 4-group 0..127
    const int ty   = tid >> 7;                          // query 4-group 0..3

    const float* kbase = qkv + (size_t)b * 512 * 768 + 256;
    const float* qbase = qkv + (size_t)b * 512 * 768;

    float acc[16];
#pragma unroll
    for (int i = 0; i < 16; ++i) acc[i] = 0.f;

    for (int h = 0; h < HH; ++h) {
        // ---- stage K transposed: Ks[e][t] ----
        // thread loads 4 consecutive t-rows at (e = lane) -> coalesced LDG.32,
        // register-transpose -> one conflict-free STS.128 per group.
#pragma unroll
        for (int m = 0; m < 8; ++m) {
            int idx = tid + m * 512;
            int e   = idx & 31;                 // == lane
            int tch = idx >> 5;                 // 0..127
            const float* g = kbase + (size_t)(4 * tch) * 768 + h * 32 + e;
            float4 v;
            v.x = g[0];
            v.y = g[768];
            v.z = g[2 * 768];
            v.w = g[3 * 768];
            *(float4*)&Ks[e * KS_STRIDE + 4 * tch] = v;
        }
        // ---- stage Q transposed: Qs[e][r] ----
        {
            int r = tid & 15, e = tid >> 4;
            Qs[e * QS_STRIDE + r] = qbase[(size_t)(s0 + r) * 768 + h * 32 + e];
        }
        __syncthreads();

        // ---- score micro-GEMM: 4 queries x 4 keys per thread ----
        float z[4][4];
#pragma unroll
        for (int i = 0; i < 4; ++i)
#pragma unroll
            for (int j = 0; j < 4; ++j) z[i][j] = 0.f;

#pragma unroll
        for (int e = 0; e < 32; ++e) {
            float4 k4 = *(const float4*)&Ks[e * KS_STRIDE + tx * 4];
            float4 q4 = *(const float4*)&Qs[e * QS_STRIDE + ty * 4];
            float kv[4] = {k4.x, k4.y, k4.z, k4.w};
            float qv[4] = {q4.x, q4.y, q4.z, q4.w};
#pragma unroll
            for (int i = 0; i < 4; ++i)
#pragma unroll
                for (int j = 0; j < 4; ++j) z[i][j] = fmaf(qv[i], kv[j], z[i][j]);
        }
#pragma unroll
        for (int i = 0; i < 4; ++i) {
            float4 o;
            o.x = z[i][0] * 0.17677669529663687f;
            o.y = z[i][1] * 0.17677669529663687f;
            o.z = z[i][2] * 0.17677669529663687f;
            o.w = z[i][3] * 0.17677669529663687f;
            *(float4*)&Ssc[(ty * 4 + i) * SS_STRIDE + tx * 4] = o;
        }
        __syncthreads();

        // ---- exact sparsemax (Michelot), warp w <-> query s0+w ----
        float zz[16];
#pragma unroll
        for (int i = 0; i < 16; ++i) zz[i] = Ssc[w * SS_STRIDE + lane + 32 * i];
        if ((s & 31) == lane) zz[s >> 5] = -CUDART_INF_F;   // diagonal mask

        float tau = -CUDART_INF_F;
        int prevc = -1;
        for (int it = 0; it < 128; ++it) {
            float sa = 0.f;
            int ca = 0;
#pragma unroll
            for (int i = 0; i < 16; ++i) {
                if (zz[i] > tau) { sa += zz[i]; ca++; }
            }
#pragma unroll
            for (int o = 16; o; o >>= 1) {
                sa += __shfl_xor_sync(0xffffffffu, sa, o);
                ca += __shfl_xor_sync(0xffffffffu, ca, o);
            }
            if (ca == prevc || ca == 0) break;
            prevc = ca;
            tau = (sa - 1.0f) / (float)ca;
        }

#pragma unroll
        for (int i = 0; i < 16; ++i)
            acc[i] += fmaxf(zz[i] - tau, 0.f) * 0.125f;     // /H
        __syncthreads();
    }

    float* dst = avg + (size_t)(b * 512 + s) * 512;
#pragma unroll
    for (int i = 0; i < 16; ++i) dst[lane + i * 32] = acc[i];
}

// ---------------------------------------------------------------------------
extern "C" void kernel_launch(void* const* d_in, const int* in_sizes, int n_in,
                              void* d_out, int out_size)
{
    const float* x  = (const float*)d_in[0];  // [32,512,256]
    const float* Wq = (const float*)d_in[1];  // [8,32,256]
    const float* bq = (const float*)d_in[2];  // [8,32]
    const float* Wk = (const float*)d_in[3];
    const float* bk = (const float*)d_in[4];
    const float* Wv = (const float*)d_in[5];  // [256,256]
    const float* bv = (const float*)d_in[6];
    const float* Wo = (const float*)d_in[7];
    const float* bo = (const float*)d_in[8];

    float* out = (float*)d_out;                        // [32,512,256]
    float* avg = out + (size_t)NROWS * DD;             // [32,512,512]

    float* qkv = nullptr;
    float* tmp = nullptr;
    cudaGetSymbolAddress((void**)&qkv, g_qkv);
    cudaGetSymbolAddress((void**)&tmp, g_tmp);

    cudaFuncSetAttribute(attn_sparsemax_kernel,
                         cudaFuncAttributeMaxDynamicSharedMemorySize, ATTN_SMEM_BYTES);

    dim3 blk(256);

    // 1) projections
    {
        dim3 grid(256 / 64, NROWS / 64);
        gemm_tn<<<grid, blk>>>(x, Wq, bq, qkv + 0,   DD, DD, DD, 768);
        gemm_tn<<<grid, blk>>>(x, Wk, bk, qkv + 256, DD, DD, DD, 768);
        gemm_tn<<<grid, blk>>>(x, Wv, bv, qkv + 512, DD, DD, DD, 768);
    }

    // 2) scores + sparsemax + head average -> avg_attention (in d_out)
    attn_sparsemax_kernel<<<NROWS / 16, 512, ATTN_SMEM_BYTES>>>(qkv, avg);

    // 3) tmp[b] = avg[b] @ v[b]
    {
        dim3 grid(256 / 64, 512 / 64, BB);
        gemm_nn_batched<<<grid, blk>>>(avg, qkv + 512, tmp,
                                       SS, SS, 768, DD,
                                       (size_t)SS * SS, (size_t)SS * 768, (size_t)SS * DD);
    }

    // 4) out = tmp @ Wo^T + bo
    {
        dim3 grid(256 / 64, NROWS / 64);
        gemm_tn<<<grid, blk>>>(tmp, Wo, bo, out, DD, DD, DD, DD);
    }
}

// round 5
// speedup vs baseline: 1.9489x; 1.0243x over previous
#include <cuda_runtime.h>
#include <cuda_bf16.h>
#include <math.h>
#include <math_constants.h>

// Problem constants
#define BB 32
#define SS 512
#define DD 256
#define HH 8
#define DHH 32
#define NROWS (BB*SS)

// Scratch (allocation is banned -> __device__ globals)
__device__ float g_qkv[(size_t)NROWS * 768];   // [row][0:256)=q, [256:512)=k, [512:768)=v
__device__ float g_tmp[(size_t)NROWS * 256];   // avg @ v result

// ---------------------------------------------------------------------------
// Packed fp32x2 helpers (Blackwell FFMA2 path — exact fp32 semantics, 2 MAC/instr)
// ---------------------------------------------------------------------------
__device__ __forceinline__ unsigned long long pack2_dup(float x) {
    unsigned long long r;
    asm("mov.b64 %0, {%1, %2};" : "=l"(r) : "f"(x), "f"(x));
    return r;
}
__device__ __forceinline__ void unpack2(unsigned long long p, float& x, float& y) {
    asm("mov.b64 {%0, %1}, %2;" : "=f"(x), "=f"(y) : "l"(p));
}
__device__ __forceinline__ unsigned long long ffma2(
    unsigned long long a, unsigned long long b, unsigned long long c) {
    unsigned long long d;
    asm("fma.rn.f32x2 %0, %1, %2, %3;" : "=l"(d) : "l"(a), "l"(b), "l"(c));
    return d;
}

// ---------------------------------------------------------------------------
// SGEMM body  C[M,N] = A[M,K] * B[N,K]^T  (+bias[n])  — FFMA2 inner loop
// 64x64 tile, KT=16, 256 threads, 4x4 microtile (held as 4x{2,2} packed).
// ---------------------------------------------------------------------------
__device__ __forceinline__ void gemm_tn_body(
    const float* __restrict__ A, const float* __restrict__ B,
    const float* __restrict__ bias, float* __restrict__ C,
    int K, int lda, int ldb, int ldc)
{
    __shared__ __align__(16) float As[16][68];
    __shared__ __align__(16) float Bs[16][68];
    const int m0 = blockIdx.y * 64;
    const int n0 = blockIdx.x * 64;
    const int tid = threadIdx.x;
    const int tx = tid & 15, ty = tid >> 4;
    const int lm = tid >> 2, lk4 = (tid & 3) * 4;

    unsigned long long c01[4], c23[4];
#pragma unroll
    for (int i = 0; i < 4; ++i) { c01[i] = 0ULL; c23[i] = 0ULL; }

    for (int k0 = 0; k0 < K; k0 += 16) {
        float4 av = *(const float4*)(A + (size_t)(m0 + lm) * lda + k0 + lk4);
        float4 bv = *(const float4*)(B + (size_t)(n0 + lm) * ldb + k0 + lk4);
        As[lk4 + 0][lm] = av.x; As[lk4 + 1][lm] = av.y;
        As[lk4 + 2][lm] = av.z; As[lk4 + 3][lm] = av.w;
        Bs[lk4 + 0][lm] = bv.x; Bs[lk4 + 1][lm] = bv.y;
        Bs[lk4 + 2][lm] = bv.z; Bs[lk4 + 3][lm] = bv.w;
        __syncthreads();
#pragma unroll
        for (int kk = 0; kk < 16; ++kk) {
            float4 a4 = *(const float4*)&As[kk][ty * 4];
            ulonglong2 b2 = *(const ulonglong2*)&Bs[kk][tx * 4];
            float a[4] = {a4.x, a4.y, a4.z, a4.w};
#pragma unroll
            for (int i = 0; i < 4; ++i) {
                unsigned long long aa = pack2_dup(a[i]);
                c01[i] = ffma2(aa, b2.x, c01[i]);
                c23[i] = ffma2(aa, b2.y, c23[i]);
            }
        }
        __syncthreads();
    }
    const int n = n0 + tx * 4;
    float b0 = bias[n + 0], b1 = bias[n + 1], b2f = bias[n + 2], b3 = bias[n + 3];
#pragma unroll
    for (int i = 0; i < 4; ++i) {
        float4 o;
        float x0, x1, x2, x3;
        unpack2(c01[i], x0, x1);
        unpack2(c23[i], x2, x3);
        o.x = x0 + b0; o.y = x1 + b1; o.z = x2 + b2f; o.w = x3 + b3;
        *(float4*)(C + (size_t)(m0 + ty * 4 + i) * ldc + n) = o;
    }
}

// Merged QKV projection: blockIdx.z selects q/k/v
__global__ __launch_bounds__(256) void gemm_qkv(
    const float* __restrict__ x,
    const float* __restrict__ Wq, const float* __restrict__ bq,
    const float* __restrict__ Wk, const float* __restrict__ bk,
    const float* __restrict__ Wv, const float* __restrict__ bv,
    float* __restrict__ qkv)
{
    const float* B; const float* bias; float* C;
    if (blockIdx.z == 0)      { B = Wq; bias = bq; C = qkv; }
    else if (blockIdx.z == 1) { B = Wk; bias = bk; C = qkv + 256; }
    else                      { B = Wv; bias = bv; C = qkv + 512; }
    gemm_tn_body(x, B, bias, C, DD, DD, DD, 768);
}

// Output projection
__global__ __launch_bounds__(256) void gemm_out(
    const float* __restrict__ tmp, const float* __restrict__ Wo,
    const float* __restrict__ bo, float* __restrict__ out)
{
    gemm_tn_body(tmp, Wo, bo, out, DD, DD, DD, DD);
}

// ---------------------------------------------------------------------------
// Batched SGEMM  C = A[M,K] * B[K,N]  — FFMA2 inner loop
// ---------------------------------------------------------------------------
__global__ __launch_bounds__(256) void gemm_nn_batched(
    const float* __restrict__ Ab, const float* __restrict__ Bb,
    float* __restrict__ Cb,
    int K, int lda, int ldb, int ldc,
    size_t strideA, size_t strideB, size_t strideC)
{
    const float* A = Ab + (size_t)blockIdx.z * strideA;
    const float* B = Bb + (size_t)blockIdx.z * strideB;
    float* C = Cb + (size_t)blockIdx.z * strideC;

    __shared__ __align__(16) float As[16][68];
    __shared__ __align__(16) float Bs[16][68];
    const int m0 = blockIdx.y * 64;
    const int n0 = blockIdx.x * 64;
    const int tid = threadIdx.x;
    const int tx = tid & 15, ty = tid >> 4;
    const int lm = tid >> 2, lk4 = (tid & 3) * 4;
    const int lkr = tid >> 4, lnq = (tid & 15) * 4;

    unsigned long long c01[4], c23[4];
#pragma unroll
    for (int i = 0; i < 4; ++i) { c01[i] = 0ULL; c23[i] = 0ULL; }

    for (int k0 = 0; k0 < K; k0 += 16) {
        float4 av = *(const float4*)(A + (size_t)(m0 + lm) * lda + k0 + lk4);
        float4 bv = *(const float4*)(B + (size_t)(k0 + lkr) * ldb + n0 + lnq);
        As[lk4 + 0][lm] = av.x; As[lk4 + 1][lm] = av.y;
        As[lk4 + 2][lm] = av.z; As[lk4 + 3][lm] = av.w;
        *(float4*)&Bs[lkr][lnq] = bv;
        __syncthreads();
#pragma unroll
        for (int kk = 0; kk < 16; ++kk) {
            float4 a4 = *(const float4*)&As[kk][ty * 4];
            ulonglong2 b2 = *(const ulonglong2*)&Bs[kk][tx * 4];
            float a[4] = {a4.x, a4.y, a4.z, a4.w};
#pragma unroll
            for (int i = 0; i < 4; ++i) {
                unsigned long long aa = pack2_dup(a[i]);
                c01[i] = ffma2(aa, b2.x, c01[i]);
                c23[i] = ffma2(aa, b2.y, c23[i]);
            }
        }
        __syncthreads();
    }
#pragma unroll
    for (int i = 0; i < 4; ++i) {
        float4 o;
        unpack2(c01[i], o.x, o.y);
        unpack2(c23[i], o.z, o.w);
        *(float4*)(C + (size_t)(m0 + ty * 4 + i) * ldc + n0 + tx * 4) = o;
    }
}

// ---------------------------------------------------------------------------
// Attention: scores via FFMA2 micro-GEMM on transposed K tile, smem score
// tile, then warp-per-query exact sparsemax (Michelot), head-avg in regs.
// ---------------------------------------------------------------------------
#define KS_STRIDE 528
#define QS_STRIDE 20
#define SS_STRIDE 520
#define ATTN_SMEM_FLOATS (32*KS_STRIDE + 32*QS_STRIDE + 16*SS_STRIDE)
#define ATTN_SMEM_BYTES (ATTN_SMEM_FLOATS * 4)

__global__ __launch_bounds__(512, 2) void attn_sparsemax_kernel(
    const float* __restrict__ qkv, float* __restrict__ avg)
{
    extern __shared__ __align__(16) float smem[];
    float* Ks  = smem;                                  // [32][KS_STRIDE] e-major
    float* Qs  = smem + 32 * KS_STRIDE;                 // [32][QS_STRIDE] e-major
    float* Ssc = Qs + 32 * QS_STRIDE;                   // [16][SS_STRIDE]

    const int tid  = threadIdx.x;
    const int w    = tid >> 5, lane = tid & 31;
    const int b    = blockIdx.x >> 5;
    const int s0   = (blockIdx.x & 31) << 4;
    const int s    = s0 + w;
    const int tx   = tid & 127;
    const int ty   = tid >> 7;

    const float* kbase = qkv + (size_t)b * 512 * 768 + 256;
    const float* qbase = qkv + (size_t)b * 512 * 768;

    float acc[16];
#pragma unroll
    for (int i = 0; i < 16; ++i) acc[i] = 0.f;

    for (int h = 0; h < HH; ++h) {
        // ---- stage K transposed: Ks[e][t] ----
#pragma unroll
        for (int m = 0; m < 8; ++m) {
            int idx = tid + m * 512;
            int e   = idx & 31;
            int tch = idx >> 5;
            const float* g = kbase + (size_t)(4 * tch) * 768 + h * 32 + e;
            float4 v;
            v.x = g[0];
            v.y = g[768];
            v.z = g[2 * 768];
            v.w = g[3 * 768];
            *(float4*)&Ks[e * KS_STRIDE + 4 * tch] = v;
        }
        // ---- stage Q transposed: Qs[e][r] ----
        {
            int r = tid & 15, e = tid >> 4;
            Qs[e * QS_STRIDE + r] = qbase[(size_t)(s0 + r) * 768 + h * 32 + e];
        }
        __syncthreads();

        // ---- score micro-GEMM: 4 queries x 4 keys per thread, FFMA2 ----
        unsigned long long z01[4], z23[4];
#pragma unroll
        for (int i = 0; i < 4; ++i) { z01[i] = 0ULL; z23[i] = 0ULL; }

#pragma unroll
        for (int e = 0; e < 32; ++e) {
            ulonglong2 k2 = *(const ulonglong2*)&Ks[e * KS_STRIDE + tx * 4];
            float4 q4 = *(const float4*)&Qs[e * QS_STRIDE + ty * 4];
            float qv[4] = {q4.x, q4.y, q4.z, q4.w};
#pragma unroll
            for (int i = 0; i < 4; ++i) {
                unsigned long long qq = pack2_dup(qv[i]);
                z01[i] = ffma2(qq, k2.x, z01[i]);
                z23[i] = ffma2(qq, k2.y, z23[i]);
            }
        }
#pragma unroll
        for (int i = 0; i < 4; ++i) {
            float4 o;
            unpack2(z01[i], o.x, o.y);
            unpack2(z23[i], o.z, o.w);
            o.x *= 0.17677669529663687f; o.y *= 0.17677669529663687f;
            o.z *= 0.17677669529663687f; o.w *= 0.17677669529663687f;
            *(float4*)&Ssc[(ty * 4 + i) * SS_STRIDE + tx * 4] = o;
        }
        __syncthreads();

        // ---- exact sparsemax (Michelot), warp w <-> query s0+w ----
        float zz[16];
#pragma unroll
        for (int i = 0; i < 16; ++i) zz[i] = Ssc[w * SS_STRIDE + lane + 32 * i];
        if ((s & 31) == lane) zz[s >> 5] = -CUDART_INF_F;   // diagonal mask

        float tau = -CUDART_INF_F;
        int prevc = -1;
        for (int it = 0; it < 128; ++it) {
            float sa = 0.f;
            int ca = 0;
#pragma unroll
            for (int i = 0; i < 16; ++i) {
                if (zz[i] > tau) { sa += zz[i]; ca++; }
            }
#pragma unroll
            for (int o = 16; o; o >>= 1) {
                sa += __shfl_xor_sync(0xffffffffu, sa, o);
                ca += __shfl_xor_sync(0xffffffffu, ca, o);
            }
            if (ca == prevc || ca == 0) break;
            prevc = ca;
            tau = (sa - 1.0f) / (float)ca;
        }

#pragma unroll
        for (int i = 0; i < 16; ++i)
            acc[i] += fmaxf(zz[i] - tau, 0.f) * 0.125f;     // /H
        __syncthreads();
    }

    float* dst = avg + (size_t)(b * 512 + s) * 512;
#pragma unroll
    for (int i = 0; i < 16; ++i) dst[lane + i * 32] = acc[i];
}

// ---------------------------------------------------------------------------
extern "C" void kernel_launch(void* const* d_in, const int* in_sizes, int n_in,
                              void* d_out, int out_size)
{
    const float* x  = (const float*)d_in[0];  // [32,512,256]
    const float* Wq = (const float*)d_in[1];  // [8,32,256]
    const float* bq = (const float*)d_in[2];  // [8,32]
    const float* Wk = (const float*)d_in[3];
    const float* bk = (const float*)d_in[4];
    const float* Wv = (const float*)d_in[5];  // [256,256]
    const float* bv = (const float*)d_in[6];
    const float* Wo = (const float*)d_in[7];
    const float* bo = (const float*)d_in[8];

    float* out = (float*)d_out;                        // [32,512,256]
    float* avg = out + (size_t)NROWS * DD;             // [32,512,512]

    float* qkv = nullptr;
    float* tmp = nullptr;
    cudaGetSymbolAddress((void**)&qkv, g_qkv);
    cudaGetSymbolAddress((void**)&tmp, g_tmp);

    cudaFuncSetAttribute(attn_sparsemax_kernel,
                         cudaFuncAttributeMaxDynamicSharedMemorySize, ATTN_SMEM_BYTES);

    dim3 blk(256);

    // 1) projections (merged: z = q/k/v)
    {
        dim3 grid(256 / 64, NROWS / 64, 3);
        gemm_qkv<<<grid, blk>>>(x, Wq, bq, Wk, bk, Wv, bv, qkv);
    }

    // 2) scores + sparsemax + head average -> avg_attention (in d_out)
    attn_sparsemax_kernel<<<NROWS / 16, 512, ATTN_SMEM_BYTES>>>(qkv, avg);

    // 3) tmp[b] = avg[b] @ v[b]
    {
        dim3 grid(256 / 64, 512 / 64, BB);
        gemm_nn_batched<<<grid, blk>>>(avg, qkv + 512, tmp,
                                       SS, SS, 768, DD,
                                       (size_t)SS * SS, (size_t)SS * 768, (size_t)SS * DD);
    }

    // 4) out = tmp @ Wo^T + bo
    {
        dim3 grid(256 / 64, NROWS / 64);
        gemm_out<<<grid, blk>>>(tmp, Wo, bo, out);
    }
}

// round 6
// speedup vs baseline: 2.0006x; 1.0265x over previous
#include <cuda_runtime.h>
#include <cuda_bf16.h>
#include <math.h>
#include <math_constants.h>

// Problem constants
#define BB 32
#define SS 512
#define DD 256
#define HH 8
#define DHH 32
#define NROWS (BB*SS)

// Scratch (allocation is banned -> __device__ globals)
__device__ float g_qkv[(size_t)NROWS * 768];   // [row][0:256)=q, [256:512)=k, [512:768)=v
__device__ float g_tmp[(size_t)NROWS * 256];   // avg @ v result

// ---------------------------------------------------------------------------
// Packed fp32x2 helpers (Blackwell FFMA2 — exact fp32 semantics, 2 MAC/instr)
// ---------------------------------------------------------------------------
__device__ __forceinline__ unsigned long long pack2_dup(float x) {
    unsigned long long r;
    asm("mov.b64 %0, {%1, %2};" : "=l"(r) : "f"(x), "f"(x));
    return r;
}
__device__ __forceinline__ void unpack2(unsigned long long p, float& x, float& y) {
    asm("mov.b64 {%0, %1}, %2;" : "=f"(x), "=f"(y) : "l"(p));
}
__device__ __forceinline__ unsigned long long ffma2(
    unsigned long long a, unsigned long long b, unsigned long long c) {
    unsigned long long d;
    asm("fma.rn.f32x2 %0, %1, %2, %3;" : "=l"(d) : "l"(a), "l"(b), "l"(c));
    return d;
}

// ---------------------------------------------------------------------------
// 128x128x16 SGEMM, 256 threads, 8x8 microtile, FFMA2, reg-prefetch.
// Smem layout k-major: As[16][132], Bs[16][132] (16B-aligned rows).
// ---------------------------------------------------------------------------
#define GSTR 132

struct TileAcc {
    unsigned long long c[8][4];
};

__device__ __forceinline__ void acc_zero(TileAcc& t) {
#pragma unroll
    for (int i = 0; i < 8; ++i)
#pragma unroll
        for (int j = 0; j < 4; ++j) t.c[i][j] = 0ULL;
}

__device__ __forceinline__ void mma_tile(
    TileAcc& t, const float* As, const float* Bs, int ty, int tx)
{
#pragma unroll
    for (int kk = 0; kk < 16; ++kk) {
        float4 a0 = *(const float4*)&As[kk * GSTR + ty * 8];
        float4 a1 = *(const float4*)&As[kk * GSTR + ty * 8 + 4];
        ulonglong2 b0 = *(const ulonglong2*)&Bs[kk * GSTR + tx * 8];
        ulonglong2 b1 = *(const ulonglong2*)&Bs[kk * GSTR + tx * 8 + 4];
        float am[8] = {a0.x, a0.y, a0.z, a0.w, a1.x, a1.y, a1.z, a1.w};
        unsigned long long bp[4] = {b0.x, b0.y, b1.x, b1.y};
#pragma unroll
        for (int i = 0; i < 8; ++i) {
            unsigned long long aa = pack2_dup(am[i]);
#pragma unroll
            for (int j = 0; j < 4; ++j) t.c[i][j] = ffma2(aa, bp[j], t.c[i][j]);
        }
    }
}

// ---- TN:  C[M,N] = A[M,K] @ B[N,K]^T + bias ----
__device__ __forceinline__ void gemm_tn_body(
    const float* __restrict__ A, const float* __restrict__ B,
    const float* __restrict__ bias, float* __restrict__ C,
    int K, int lda, int ldb, int ldc)
{
    __shared__ __align__(16) float As[16 * GSTR];
    __shared__ __align__(16) float Bs[16 * GSTR];
    const int m0 = blockIdx.y * 128;
    const int n0 = blockIdx.x * 128;
    const int tid = threadIdx.x;
    const int tx = tid & 15, ty = tid >> 4;
    const int lr = tid >> 1;            // 0..127 row (m or n)
    const int lk = (tid & 1) * 8;       // k sub-offset 0/8

    const float* pA = A + (size_t)(m0 + lr) * lda + lk;
    const float* pB = B + (size_t)(n0 + lr) * ldb + lk;

    TileAcc t; acc_zero(t);

    float4 pa0 = *(const float4*)(pA);
    float4 pa1 = *(const float4*)(pA + 4);
    float4 pb0 = *(const float4*)(pB);
    float4 pb1 = *(const float4*)(pB + 4);

    for (int k0 = 0; k0 < K; k0 += 16) {
        // store staged regs (transpose to k-major)
        float av[8] = {pa0.x, pa0.y, pa0.z, pa0.w, pa1.x, pa1.y, pa1.z, pa1.w};
        float bv[8] = {pb0.x, pb0.y, pb0.z, pb0.w, pb1.x, pb1.y, pb1.z, pb1.w};
#pragma unroll
        for (int i = 0; i < 8; ++i) {
            As[(lk + i) * GSTR + lr] = av[i];
            Bs[(lk + i) * GSTR + lr] = bv[i];
        }
        __syncthreads();
        if (k0 + 16 < K) {
            pa0 = *(const float4*)(pA + k0 + 16);
            pa1 = *(const float4*)(pA + k0 + 20);
            pb0 = *(const float4*)(pB + k0 + 16);
            pb1 = *(const float4*)(pB + k0 + 20);
        }
        mma_tile(t, As, Bs, ty, tx);
        __syncthreads();
    }

    const int n = n0 + tx * 8;
    float4 bb0 = *(const float4*)(bias + n);
    float4 bb1 = *(const float4*)(bias + n + 4);
#pragma unroll
    for (int i = 0; i < 8; ++i) {
        float4 o0, o1;
        unpack2(t.c[i][0], o0.x, o0.y);
        unpack2(t.c[i][1], o0.z, o0.w);
        unpack2(t.c[i][2], o1.x, o1.y);
        unpack2(t.c[i][3], o1.z, o1.w);
        o0.x += bb0.x; o0.y += bb0.y; o0.z += bb0.z; o0.w += bb0.w;
        o1.x += bb1.x; o1.y += bb1.y; o1.z += bb1.z; o1.w += bb1.w;
        float* cp = C + (size_t)(m0 + ty * 8 + i) * ldc + n;
        *(float4*)cp = o0;
        *(float4*)(cp + 4) = o1;
    }
}

// Merged QKV projection: blockIdx.z selects q/k/v
__global__ __launch_bounds__(256) void gemm_qkv(
    const float* __restrict__ x,
    const float* __restrict__ Wq, const float* __restrict__ bq,
    const float* __restrict__ Wk, const float* __restrict__ bk,
    const float* __restrict__ Wv, const float* __restrict__ bv,
    float* __restrict__ qkv)
{
    const float* B; const float* bias; float* C;
    if (blockIdx.z == 0)      { B = Wq; bias = bq; C = qkv; }
    else if (blockIdx.z == 1) { B = Wk; bias = bk; C = qkv + 256; }
    else                      { B = Wv; bias = bv; C = qkv + 512; }
    gemm_tn_body(x, B, bias, C, DD, DD, DD, 768);
}

__global__ __launch_bounds__(256) void gemm_out(
    const float* __restrict__ tmp, const float* __restrict__ Wo,
    const float* __restrict__ bo, float* __restrict__ out)
{
    gemm_tn_body(tmp, Wo, bo, out, DD, DD, DD, DD);
}

// ---- NN batched:  C = A[M,K] @ B[K,N]  (B N-contiguous, ldb stride) ----
__global__ __launch_bounds__(256) void gemm_nn_batched(
    const float* __restrict__ Ab, const float* __restrict__ Bb,
    float* __restrict__ Cb,
    int K, int lda, int ldb, int ldc,
    size_t strideA, size_t strideB, size_t strideC)
{
    const float* A = Ab + (size_t)blockIdx.z * strideA;
    const float* B = Bb + (size_t)blockIdx.z * strideB;
    float* C = Cb + (size_t)blockIdx.z * strideC;

    __shared__ __align__(16) float As[16 * GSTR];
    __shared__ __align__(16) float Bs[16 * GSTR];
    const int m0 = blockIdx.y * 128;
    const int n0 = blockIdx.x * 128;
    const int tid = threadIdx.x;
    const int tx = tid & 15, ty = tid >> 4;
    const int lr = tid >> 1;            // A loader: row m
    const int lk = (tid & 1) * 8;
    const int bkr = tid >> 5;           // B loader: k-row 0..7 (+8)
    const int bn4 = (tid & 31) * 4;     // n offset

    const float* pA = A + (size_t)(m0 + lr) * lda + lk;
    const float* pB = B + n0 + bn4;

    TileAcc t; acc_zero(t);

    float4 pa0 = *(const float4*)(pA);
    float4 pa1 = *(const float4*)(pA + 4);
    float4 pb0 = *(const float4*)(pB + (size_t)bkr * ldb);
    float4 pb1 = *(const float4*)(pB + (size_t)(bkr + 8) * ldb);

    for (int k0 = 0; k0 < K; k0 += 16) {
        float av[8] = {pa0.x, pa0.y, pa0.z, pa0.w, pa1.x, pa1.y, pa1.z, pa1.w};
#pragma unroll
        for (int i = 0; i < 8; ++i) As[(lk + i) * GSTR + lr] = av[i];
        *(float4*)&Bs[bkr * GSTR + bn4] = pb0;
        *(float4*)&Bs[(bkr + 8) * GSTR + bn4] = pb1;
        __syncthreads();
        if (k0 + 16 < K) {
            pa0 = *(const float4*)(pA + k0 + 16);
            pa1 = *(const float4*)(pA + k0 + 20);
            pb0 = *(const float4*)(pB + (size_t)(k0 + 16 + bkr) * ldb);
            pb1 = *(const float4*)(pB + (size_t)(k0 + 24 + bkr) * ldb);
        }
        mma_tile(t, As, Bs, ty, tx);
        __syncthreads();
    }

#pragma unroll
    for (int i = 0; i < 8; ++i) {
        float4 o0, o1;
        unpack2(t.c[i][0], o0.x, o0.y);
        unpack2(t.c[i][1], o0.z, o0.w);
        unpack2(t.c[i][2], o1.x, o1.y);
        unpack2(t.c[i][3], o1.z, o1.w);
        float* cp = C + (size_t)(m0 + ty * 8 + i) * ldc + n0 + tx * 8;
        *(float4*)cp = o0;
        *(float4*)(cp + 4) = o1;
    }
}

// ---------------------------------------------------------------------------
// Attention: scores via FFMA2 micro-GEMM on transposed K tile, smem score
// tile, then warp-per-query exact sparsemax (Michelot), head-avg in regs.
// ---------------------------------------------------------------------------
#define KS_STRIDE 528
#define QS_STRIDE 20
#define SS_STRIDE 520
#define ATTN_SMEM_FLOATS (32*KS_STRIDE + 32*QS_STRIDE + 16*SS_STRIDE)
#define ATTN_SMEM_BYTES (ATTN_SMEM_FLOATS * 4)

__global__ __launch_bounds__(512, 2) void attn_sparsemax_kernel(
    const float* __restrict__ qkv, float* __restrict__ avg)
{
    extern __shared__ __align__(16) float smem[];
    float* Ks  = smem;                                  // [32][KS_STRIDE] e-major
    float* Qs  = smem + 32 * KS_STRIDE;                 // [32][QS_STRIDE] e-major
    float* Ssc = Qs + 32 * QS_STRIDE;                   // [16][SS_STRIDE]

    const int tid  = threadIdx.x;
    const int w    = tid >> 5, lane = tid & 31;
    const int b    = blockIdx.x >> 5;
    const int s0   = (blockIdx.x & 31) << 4;
    const int s    = s0 + w;
    const int tx   = tid & 127;
    const int ty   = tid >> 7;

    const float* kbase = qkv + (size_t)b * 512 * 768 + 256;
    const float* qbase = qkv + (size_t)b * 512 * 768;

    float acc[16];
#pragma unroll
    for (int i = 0; i < 16; ++i) acc[i] = 0.f;

    for (int h = 0; h < HH; ++h) {
        // ---- stage K transposed: Ks[e][t] ----
#pragma unroll
        for (int m = 0; m < 8; ++m) {
            int idx = tid + m * 512;
            int e   = idx & 31;
            int tch = idx >> 5;
            const float* g = kbase + (size_t)(4 * tch) * 768 + h * 32 + e;
            float4 v;
            v.x = g[0];
            v.y = g[768];
            v.z = g[2 * 768];
            v.w = g[3 * 768];
            *(float4*)&Ks[e * KS_STRIDE + 4 * tch] = v;
        }
        // ---- stage Q transposed: Qs[e][r] ----
        {
            int r = tid & 15, e = tid >> 4;
            Qs[e * QS_STRIDE + r] = qbase[(size_t)(s0 + r) * 768 + h * 32 + e];
        }
        __syncthreads();

        // ---- score micro-GEMM: 4 queries x 4 keys per thread, FFMA2 ----
        unsigned long long z01[4], z23[4];
#pragma unroll
        for (int i = 0; i < 4; ++i) { z01[i] = 0ULL; z23[i] = 0ULL; }

#pragma unroll
        for (int e = 0; e < 32; ++e) {
            ulonglong2 k2 = *(const ulonglong2*)&Ks[e * KS_STRIDE + tx * 4];
            float4 q4 = *(const float4*)&Qs[e * QS_STRIDE + ty * 4];
            float qv[4] = {q4.x, q4.y, q4.z, q4.w};
#pragma unroll
            for (int i = 0; i < 4; ++i) {
                unsigned long long qq = pack2_dup(qv[i]);
                z01[i] = ffma2(qq, k2.x, z01[i]);
                z23[i] = ffma2(qq, k2.y, z23[i]);
            }
        }
#pragma unroll
        for (int i = 0; i < 4; ++i) {
            float4 o;
            unpack2(z01[i], o.x, o.y);
            unpack2(z23[i], o.z, o.w);
            o.x *= 0.17677669529663687f; o.y *= 0.17677669529663687f;
            o.z *= 0.17677669529663687f; o.w *= 0.17677669529663687f;
            *(float4*)&Ssc[(ty * 4 + i) * SS_STRIDE + tx * 4] = o;
        }
        __syncthreads();

        // ---- exact sparsemax (Michelot), warp w <-> query s0+w ----
        float zz[16];
#pragma unroll
        for (int i = 0; i < 16; ++i) zz[i] = Ssc[w * SS_STRIDE + lane + 32 * i];
        if ((s & 31) == lane) zz[s >> 5] = -CUDART_INF_F;   // diagonal mask

        float tau = -CUDART_INF_F;
        int prevc = -1;
        for (int it = 0; it < 128; ++it) {
            float sa = 0.f;
            int ca = 0;
#pragma unroll
            for (int i = 0; i < 16; ++i) {
                if (zz[i] > tau) { sa += zz[i]; ca++; }
            }
#pragma unroll
            for (int o = 16; o; o >>= 1) {
                sa += __shfl_xor_sync(0xffffffffu, sa, o);
                ca += __shfl_xor_sync(0xffffffffu, ca, o);
            }
            if (ca == prevc || ca == 0) break;
            prevc = ca;
            tau = (sa - 1.0f) / (float)ca;
        }

#pragma unroll
        for (int i = 0; i < 16; ++i)
            acc[i] += fmaxf(zz[i] - tau, 0.f) * 0.125f;     // /H
        __syncthreads();
    }

    float* dst = avg + (size_t)(b * 512 + s) * 512;
#pragma unroll
    for (int i = 0; i < 16; ++i) dst[lane + i * 32] = acc[i];
}

// ---------------------------------------------------------------------------
extern "C" void kernel_launch(void* const* d_in, const int* in_sizes, int n_in,
                              void* d_out, int out_size)
{
    const float* x  = (const float*)d_in[0];  // [32,512,256]
    const float* Wq = (const float*)d_in[1];  // [8,32,256]
    const float* bq = (const float*)d_in[2];  // [8,32]
    const float* Wk = (const float*)d_in[3];
    const float* bk = (const float*)d_in[4];
    const float* Wv = (const float*)d_in[5];  // [256,256]
    const float* bv = (const float*)d_in[6];
    const float* Wo = (const float*)d_in[7];
    const float* bo = (const float*)d_in[8];

    float* out = (float*)d_out;                        // [32,512,256]
    float* avg = out + (size_t)NROWS * DD;             // [32,512,512]

    float* qkv = nullptr;
    float* tmp = nullptr;
    cudaGetSymbolAddress((void**)&qkv, g_qkv);
    cudaGetSymbolAddress((void**)&tmp, g_tmp);

    cudaFuncSetAttribute(attn_sparsemax_kernel,
                         cudaFuncAttributeMaxDynamicSharedMemorySize, ATTN_SMEM_BYTES);

    dim3 blk(256);

    // 1) projections (merged: z = q/k/v)   M=16384, N=256, K=256
    {
        dim3 grid(256 / 128, NROWS / 128, 3);
        gemm_qkv<<<grid, blk>>>(x, Wq, bq, Wk, bk, Wv, bv, qkv);
    }

    // 2) scores + sparsemax + head average -> avg_attention (in d_out)
    attn_sparsemax_kernel<<<NROWS / 16, 512, ATTN_SMEM_BYTES>>>(qkv, avg);

    // 3) tmp[b] = avg[b] @ v[b]   M=512, N=256, K=512
    {
        dim3 grid(256 / 128, 512 / 128, BB);
        gemm_nn_batched<<<grid, blk>>>(avg, qkv + 512, tmp,
                                       SS, SS, 768, DD,
                                       (size_t)SS * SS, (size_t)SS * 768, (size_t)SS * DD);
    }

    // 4) out = tmp @ Wo^T + bo   M=16384, N=256, K=256
    {
        dim3 grid(256 / 128, NROWS / 128);
        gemm_out<<<grid, blk>>>(tmp, Wo, bo, out);
    }
}

// round 8
// speedup vs baseline: 2.5362x; 1.2678x over previous
#include <cuda_runtime.h>
#include <cuda_bf16.h>
#include <cstdint>
#include <math.h>
#include <math_constants.h>

// Problem constants
#define BB 32
#define SS 512
#define DD 256
#define HH 8
#define DHH 32
#define NROWS (BB*SS)

// Scratch (__device__ globals; allocation is banned)
__device__ float g_qkv[(size_t)NROWS * 768];   // [row][0:256)=q, [256:512)=k, [512:768)=v
__device__ float g_tmp[(size_t)NROWS * 256];   // avg @ v result

// ---------------------------------------------------------------------------
// bf16 split + pack helpers (3xBF16 fp32 emulation)
// ---------------------------------------------------------------------------
__device__ __forceinline__ void splitpk(float x, float y, uint32_t& h, uint32_t& l) {
    __nv_bfloat16 hx = __float2bfloat16(x), hy = __float2bfloat16(y);
    float rx = x - __bfloat162float(hx);
    float ry = y - __bfloat162float(hy);
    __nv_bfloat16 lx = __float2bfloat16(rx), ly = __float2bfloat16(ry);
    h = (uint32_t)__bfloat16_as_ushort(hx) | ((uint32_t)__bfloat16_as_ushort(hy) << 16);
    l = (uint32_t)__bfloat16_as_ushort(lx) | ((uint32_t)__bfloat16_as_ushort(ly) << 16);
}

__device__ __forceinline__ uint32_t cvta_s(const void* p) {
    return (uint32_t)__cvta_generic_to_shared(p);
}

__device__ __forceinline__ void ldmx4(uint32_t r[4], uint32_t addr) {
    asm volatile("ldmatrix.sync.aligned.m8n8.x4.shared.b16 {%0,%1,%2,%3}, [%4];"
                 : "=r"(r[0]), "=r"(r[1]), "=r"(r[2]), "=r"(r[3]) : "r"(addr));
}
__device__ __forceinline__ void ldmx4t(uint32_t r[4], uint32_t addr) {
    asm volatile("ldmatrix.sync.aligned.m8n8.x4.trans.shared.b16 {%0,%1,%2,%3}, [%4];"
                 : "=r"(r[0]), "=r"(r[1]), "=r"(r[2]), "=r"(r[3]) : "r"(addr));
}

__device__ __forceinline__ void mma16816(float c[4], const uint32_t a[4],
                                         uint32_t b0, uint32_t b1) {
    asm volatile(
        "mma.sync.aligned.m16n8k16.row.col.f32.bf16.bf16.f32 "
        "{%0,%1,%2,%3}, {%4,%5,%6,%7}, {%8,%9}, {%0,%1,%2,%3};"
        : "+f"(c[0]), "+f"(c[1]), "+f"(c[2]), "+f"(c[3])
        : "r"(a[0]), "r"(a[1]), "r"(a[2]), "r"(a[3]), "r"(b0), "r"(b1));
}

// ---------------------------------------------------------------------------
// Tile strides (bf16 elements per row, padded for conflict-free ldmatrix)
// ---------------------------------------------------------------------------
#define AT_STR 40    // K-major tiles: 32 k + 8 pad (80B row: banks perfectly spread)
#define BN_STR 136   // NN B tile [k][n]: 128 n + 8 pad (272B row)

// Stage a 128x32 fp32 K-contig tile -> hi/lo bf16 smem (row stride AT_STR)
// (values pre-loaded in f[4] = 16 floats for row=tid>>1, khalf=(tid&1)*16)
__device__ __forceinline__ void stage_tn(uint16_t* hi, uint16_t* lo,
                                         const float4 f[4], int tid) {
    int row = tid >> 1, kh = (tid & 1) * 16;
    uint4 H0, H1, L0, L1;
    splitpk(f[0].x, f[0].y, H0.x, L0.x); splitpk(f[0].z, f[0].w, H0.y, L0.y);
    splitpk(f[1].x, f[1].y, H0.z, L0.z); splitpk(f[1].z, f[1].w, H0.w, L0.w);
    splitpk(f[2].x, f[2].y, H1.x, L1.x); splitpk(f[2].z, f[2].w, H1.y, L1.y);
    splitpk(f[3].x, f[3].y, H1.z, L1.z); splitpk(f[3].z, f[3].w, H1.w, L1.w);
    *(uint4*)(hi + row * AT_STR + kh)     = H0;
    *(uint4*)(hi + row * AT_STR + kh + 8) = H1;
    *(uint4*)(lo + row * AT_STR + kh)     = L0;
    *(uint4*)(lo + row * AT_STR + kh + 8) = L1;
}

// Stage a 32x128 fp32 N-contig tile -> hi/lo bf16 smem [k][n] (stride BN_STR)
__device__ __forceinline__ void stage_nn_b(uint16_t* hi, uint16_t* lo,
                                           const float4 f[4], int tid) {
    int k = tid >> 3, nq = (tid & 7) * 16;
    uint4 H0, H1, L0, L1;
    splitpk(f[0].x, f[0].y, H0.x, L0.x); splitpk(f[0].z, f[0].w, H0.y, L0.y);
    splitpk(f[1].x, f[1].y, H0.z, L0.z); splitpk(f[1].z, f[1].w, H0.w, L0.w);
    splitpk(f[2].x, f[2].y, H1.x, L1.x); splitpk(f[2].z, f[2].w, H1.y, L1.y);
    splitpk(f[3].x, f[3].y, H1.z, L1.z); splitpk(f[3].z, f[3].w, H1.w, L1.w);
    *(uint4*)(hi + k * BN_STR + nq)     = H0;
    *(uint4*)(hi + k * BN_STR + nq + 8) = H1;
    *(uint4*)(lo + k * BN_STR + nq)     = L0;
    *(uint4*)(lo + k * BN_STR + nq + 8) = L1;
}

// Warp-level compute of one K-chunk (32): 2 k16 steps, 3 split-combos.
// TRANSB=false: B tile K-major [n][k] stride AT_STR (non-trans ldmatrix)
// TRANSB=true : B tile [k][n] stride BN_STR (.trans ldmatrix)
template<bool TRANSB>
__device__ __forceinline__ void compute_chunk(
    float c[4][4][4],
    const uint16_t* sAhi, const uint16_t* sAlo,
    const uint16_t* sBhi, const uint16_t* sBlo,
    int lane, int mrow0, int ncol0)
{
    const int lr = lane & 7, lg = lane >> 3;
#pragma unroll
    for (int k16 = 0; k16 < 32; k16 += 16) {
        uint32_t ah[4][4], al[4][4];
        uint32_t aoff = (uint32_t)(((mrow0 + (lane & 15)) * AT_STR + k16 + ((lane >> 4) << 3)) * 2);
#pragma unroll
        for (int mi = 0; mi < 4; ++mi) {
            ldmx4(ah[mi], cvta_s(sAhi) + aoff + mi * (16 * AT_STR * 2));
            ldmx4(al[mi], cvta_s(sAlo) + aoff + mi * (16 * AT_STR * 2));
        }
        uint32_t bh[2][4], bl[2][4];
#pragma unroll
        for (int nb = 0; nb < 2; ++nb) {
            uint32_t boff;
            if (TRANSB) {
                boff = (uint32_t)(((k16 + lr + ((lg & 1) << 3)) * BN_STR
                                   + ncol0 + nb * 16 + ((lg & 2) << 2)) * 2);
                ldmx4t(bh[nb], cvta_s(sBhi) + boff);
                ldmx4t(bl[nb], cvta_s(sBlo) + boff);
            } else {
                boff = (uint32_t)(((ncol0 + nb * 16 + lr + ((lg & 2) << 2)) * AT_STR
                                   + k16 + ((lg & 1) << 3)) * 2);
                ldmx4(bh[nb], cvta_s(sBhi) + boff);
                ldmx4(bl[nb], cvta_s(sBlo) + boff);
            }
        }
#pragma unroll
        for (int mi = 0; mi < 4; ++mi)
#pragma unroll
            for (int nb = 0; nb < 2; ++nb)
#pragma unroll
                for (int half = 0; half < 2; ++half) {
                    float* cc = c[mi][nb * 2 + half];
                    mma16816(cc, ah[mi], bh[nb][half * 2], bh[nb][half * 2 + 1]);  // hi*hi
                    mma16816(cc, ah[mi], bl[nb][half * 2], bl[nb][half * 2 + 1]);  // hi*lo
                    mma16816(cc, al[mi], bh[nb][half * 2], bh[nb][half * 2 + 1]);  // lo*hi
                }
    }
}

__device__ __forceinline__ void epilogue_store(
    float c[4][4][4], float* __restrict__ C, const float* __restrict__ bias,
    int ldc, int m0, int cn0, int mrow0, int ncol0, int lane)
{
#pragma unroll
    for (int mi = 0; mi < 4; ++mi) {
        int r = m0 + mrow0 + mi * 16 + (lane >> 2);
#pragma unroll
        for (int ni = 0; ni < 4; ++ni) {
            int cl = ncol0 + ni * 8 + ((lane & 3) << 1);
            float b0 = 0.f, b1 = 0.f;
            if (bias) { b0 = bias[cl]; b1 = bias[cl + 1]; }
            float2 v0 = make_float2(c[mi][ni][0] + b0, c[mi][ni][1] + b1);
            float2 v1 = make_float2(c[mi][ni][2] + b0, c[mi][ni][3] + b1);
            *(float2*)(C + (size_t)r * ldc + cn0 + cl) = v0;
            *(float2*)(C + (size_t)(r + 8) * ldc + cn0 + cl) = v1;
        }
    }
}

// ---------------------------------------------------------------------------
// TN GEMM body: C[.][cn0+128) = A[M,K] @ B(128 rows,K)^T + bias  (K-contig both)
// ---------------------------------------------------------------------------
__device__ __forceinline__ void gemm_tn_mma_body(
    const float* __restrict__ A, const float* __restrict__ B,
    const float* __restrict__ bias, float* __restrict__ C,
    int K, int lda, int ldb, int ldc, int m0, int cn0)
{
    __shared__ __align__(16) uint16_t sAhi[128 * AT_STR];
    __shared__ __align__(16) uint16_t sAlo[128 * AT_STR];
    __shared__ __align__(16) uint16_t sBhi[128 * AT_STR];
    __shared__ __align__(16) uint16_t sBlo[128 * AT_STR];

    const int tid = threadIdx.x;
    const int lane = tid & 31, warp = tid >> 5;
    const int mrow0 = (warp & 1) * 64, ncol0 = (warp >> 1) * 32;
    const int row = tid >> 1, kh = (tid & 1) * 16;

    float c[4][4][4];
#pragma unroll
    for (int i = 0; i < 4; ++i)
#pragma unroll
        for (int j = 0; j < 4; ++j)
#pragma unroll
            for (int q = 0; q < 4; ++q) c[i][j][q] = 0.f;

    const float* pA = A + (size_t)(m0 + row) * lda + kh;
    const float* pB = B + (size_t)row * ldb + kh;

    float4 fa[4], fb[4];
#pragma unroll
    for (int i = 0; i < 4; ++i) {
        fa[i] = *(const float4*)(pA + i * 4);
        fb[i] = *(const float4*)(pB + i * 4);
    }

    for (int k0 = 0; k0 < K; k0 += 32) {
        stage_tn(sAhi, sAlo, fa, tid);
        stage_tn(sBhi, sBlo, fb, tid);
        __syncthreads();
        if (k0 + 32 < K) {
#pragma unroll
            for (int i = 0; i < 4; ++i) {
                fa[i] = *(const float4*)(pA + k0 + 32 + i * 4);
                fb[i] = *(const float4*)(pB + k0 + 32 + i * 4);
            }
        }
        compute_chunk<false>(c, sAhi, sAlo, sBhi, sBlo, lane, mrow0, ncol0);
        __syncthreads();
    }
    epilogue_store(c, C, bias, ldc, m0, cn0, mrow0, ncol0, lane);
}

// QKV projection: blockIdx.x = 0..5 selects 128-col slab of [q|k|v]
__global__ __launch_bounds__(256) void mma_qkv(
    const float* __restrict__ x,
    const float* __restrict__ Wq, const float* __restrict__ bq,
    const float* __restrict__ Wk, const float* __restrict__ bk,
    const float* __restrict__ Wv, const float* __restrict__ bv,
    float* __restrict__ qkv)
{
    const int z = blockIdx.x;
    const int m0 = blockIdx.y * 128;
    const float* B; const float* bias;
    if (z < 2)      { B = Wq + (size_t)z * 128 * 256;       bias = bq + z * 128; }
    else if (z < 4) { B = Wk + (size_t)(z - 2) * 128 * 256; bias = bk + (z - 2) * 128; }
    else            { B = Wv + (size_t)(z - 4) * 128 * 256; bias = bv + (z - 4) * 128; }
    gemm_tn_mma_body(x, B, bias, qkv, 256, 256, 256, 768, m0, z * 128);
}

// out = tmp @ Wo^T + bo
__global__ __launch_bounds__(256) void mma_out(
    const float* __restrict__ tmp, const float* __restrict__ Wo,
    const float* __restrict__ bo, float* __restrict__ out)
{
    const int n0 = blockIdx.x * 128;
    const int m0 = blockIdx.y * 128;
    gemm_tn_mma_body(tmp, Wo + (size_t)n0 * 256, bo + n0, out, 256, 256, 256, 256, m0, n0);
}

// ---------------------------------------------------------------------------
// NN batched: tmp[b] = avg[b](512x512) @ v[b](512x256, rows strided 768)
// ---------------------------------------------------------------------------
__global__ __launch_bounds__(256) void mma_nn(
    const float* __restrict__ avg, const float* __restrict__ qkv,
    float* __restrict__ tmp)
{
    __shared__ __align__(16) uint16_t sAhi[128 * AT_STR];
    __shared__ __align__(16) uint16_t sAlo[128 * AT_STR];
    __shared__ __align__(16) uint16_t sBhi[32 * BN_STR];
    __shared__ __align__(16) uint16_t sBlo[32 * BN_STR];

    const int tid = threadIdx.x;
    const int lane = tid & 31, warp = tid >> 5;
    const int mrow0 = (warp & 1) * 64, ncol0 = (warp >> 1) * 32;
    const int n0 = blockIdx.x * 128;
    const int m0 = blockIdx.y * 128;
    const int b  = blockIdx.z;

    const float* A = avg + (size_t)b * 512 * 512;
    const float* B = qkv + (size_t)b * 512 * 768 + 512;   // v, ldb=768, N-contig rows

    float c[4][4][4];
#pragma unroll
    for (int i = 0; i < 4; ++i)
#pragma unroll
        for (int j = 0; j < 4; ++j)
#pragma unroll
            for (int q = 0; q < 4; ++q) c[i][j][q] = 0.f;

    const int row = tid >> 1, kh = (tid & 1) * 16;       // A loader
    const int bk = tid >> 3, bn = (tid & 7) * 16;        // B loader
    const float* pA = A + (size_t)(m0 + row) * 512 + kh;
    const float* pB = B + n0 + bn;

    float4 fa[4], fb[4];
#pragma unroll
    for (int i = 0; i < 4; ++i) {
        fa[i] = *(const float4*)(pA + i * 4);
        fb[i] = *(const float4*)(pB + (size_t)bk * 768 + i * 4);
    }

    for (int k0 = 0; k0 < 512; k0 += 32) {
        stage_tn(sAhi, sAlo, fa, tid);
        stage_nn_b(sBhi, sBlo, fb, tid);
        __syncthreads();
        if (k0 + 32 < 512) {
#pragma unroll
            for (int i = 0; i < 4; ++i) {
                fa[i] = *(const float4*)(pA + k0 + 32 + i * 4);
                fb[i] = *(const float4*)(pB + (size_t)(k0 + 32 + bk) * 768 + i * 4);
            }
        }
        compute_chunk<true>(c, sAhi, sAlo, sBhi, sBlo, lane, mrow0, ncol0);
        __syncthreads();
    }
    epilogue_store(c, tmp, nullptr, 256, b * 512 + m0, n0, mrow0, ncol0, lane);
}

// ---------------------------------------------------------------------------
// Attention (unchanged from R6): FFMA2 score micro-GEMM + exact sparsemax.
// ---------------------------------------------------------------------------
__device__ __forceinline__ unsigned long long pack2_dup(float x) {
    unsigned long long r;
    asm("mov.b64 %0, {%1, %2};" : "=l"(r) : "f"(x), "f"(x));
    return r;
}
__device__ __forceinline__ void unpack2(unsigned long long p, float& x, float& y) {
    asm("mov.b64 {%0, %1}, %2;" : "=f"(x), "=f"(y) : "l"(p));
}
__device__ __forceinline__ unsigned long long ffma2(
    unsigned long long a, unsigned long long b, unsigned long long c) {
    unsigned long long d;
    asm("fma.rn.f32x2 %0, %1, %2, %3;" : "=l"(d) : "l"(a), "l"(b), "l"(c));
    return d;
}

#define KS_STRIDE 528
#define QS_STRIDE 20
#define SC_STRIDE 520
#define ATTN_SMEM_FLOATS (32*KS_STRIDE + 32*QS_STRIDE + 16*SC_STRIDE)
#define ATTN_SMEM_BYTES (ATTN_SMEM_FLOATS * 4)

__global__ __launch_bounds__(512, 2) void attn_sparsemax_kernel(
    const float* __restrict__ qkv, float* __restrict__ avg)
{
    extern __shared__ __align__(16) float fsm[];
    float* Ks  = fsm;
    float* Qs  = fsm + 32 * KS_STRIDE;
    float* Ssc = Qs + 32 * QS_STRIDE;

    const int tid  = threadIdx.x;
    const int w    = tid >> 5, lane = tid & 31;
    const int b    = blockIdx.x >> 5;
    const int s0   = (blockIdx.x & 31) << 4;
    const int s    = s0 + w;
    const int tx   = tid & 127;
    const int ty   = tid >> 7;

    const float* kbase = qkv + (size_t)b * 512 * 768 + 256;
    const float* qbase = qkv + (size_t)b * 512 * 768;

    float acc[16];
#pragma unroll
    for (int i = 0; i < 16; ++i) acc[i] = 0.f;

    for (int h = 0; h < HH; ++h) {
#pragma unroll
        for (int m = 0; m < 8; ++m) {
            int idx = tid + m * 512;
            int e   = idx & 31;
            int tch = idx >> 5;
            const float* g = kbase + (size_t)(4 * tch) * 768 + h * 32 + e;
            float4 v;
            v.x = g[0];
            v.y = g[768];
            v.z = g[2 * 768];
            v.w = g[3 * 768];
            *(float4*)&Ks[e * KS_STRIDE + 4 * tch] = v;
        }
        {
            int r = tid & 15, e = tid >> 4;
            Qs[e * QS_STRIDE + r] = qbase[(size_t)(s0 + r) * 768 + h * 32 + e];
        }
        __syncthreads();

        unsigned long long z01[4], z23[4];
#pragma unroll
        for (int i = 0; i < 4; ++i) { z01[i] = 0ULL; z23[i] = 0ULL; }

#pragma unroll
        for (int e = 0; e < 32; ++e) {
            ulonglong2 k2 = *(const ulonglong2*)&Ks[e * KS_STRIDE + tx * 4];
            float4 q4 = *(const float4*)&Qs[e * QS_STRIDE + ty * 4];
            float qv[4] = {q4.x, q4.y, q4.z, q4.w};
#pragma unroll
            for (int i = 0; i < 4; ++i) {
                unsigned long long qq = pack2_dup(qv[i]);
                z01[i] = ffma2(qq, k2.x, z01[i]);
                z23[i] = ffma2(qq, k2.y, z23[i]);
            }
        }
#pragma unroll
        for (int i = 0; i < 4; ++i) {
            float4 o;
            unpack2(z01[i], o.x, o.y);
            unpack2(z23[i], o.z, o.w);
            o.x *= 0.17677669529663687f; o.y *= 0.17677669529663687f;
            o.z *= 0.17677669529663687f; o.w *= 0.17677669529663687f;
            *(float4*)&Ssc[(ty * 4 + i) * SC_STRIDE + tx * 4] = o;
        }
        __syncthreads();

        float zz[16];
#pragma unroll
        for (int i = 0; i < 16; ++i) zz[i] = Ssc[w * SC_STRIDE + lane + 32 * i];
        if ((s & 31) == lane) zz[s >> 5] = -CUDART_INF_F;

        float tau = -CUDART_INF_F;
        int prevc = -1;
        for (int it = 0; it < 128; ++it) {
            float sa = 0.f;
            int ca = 0;
#pragma unroll
            for (int i = 0; i < 16; ++i) {
                if (zz[i] > tau) { sa += zz[i]; ca++; }
            }
#pragma unroll
            for (int o = 16; o; o >>= 1) {
                sa += __shfl_xor_sync(0xffffffffu, sa, o);
                ca += __shfl_xor_sync(0xffffffffu, ca, o);
            }
            if (ca == prevc || ca == 0) break;
            prevc = ca;
            tau = (sa - 1.0f) / (float)ca;
        }

#pragma unroll
        for (int i = 0; i < 16; ++i)
            acc[i] += fmaxf(zz[i] - tau, 0.f) * 0.125f;
        __syncthreads();
    }

    float* dst = avg + (size_t)(b * 512 + s) * 512;
#pragma unroll
    for (int i = 0; i < 16; ++i) dst[lane + i * 32] = acc[i];
}

// ---------------------------------------------------------------------------
extern "C" void kernel_launch(void* const* d_in, const int* in_sizes, int n_in,
                              void* d_out, int out_size)
{
    const float* x  = (const float*)d_in[0];
    const float* Wq = (const float*)d_in[1];
    const float* bq = (const float*)d_in[2];
    const float* Wk = (const float*)d_in[3];
    const float* bk = (const float*)d_in[4];
    const float* Wv = (const float*)d_in[5];
    const float* bv = (const float*)d_in[6];
    const float* Wo = (const float*)d_in[7];
    const float* bo = (const float*)d_in[8];

    float* out = (float*)d_out;                        // [32,512,256]
    float* avg = out + (size_t)NROWS * DD;             // [32,512,512]

    float* qkv = nullptr;
    float* tmp = nullptr;
    cudaGetSymbolAddress((void**)&qkv, g_qkv);
    cudaGetSymbolAddress((void**)&tmp, g_tmp);

    cudaFuncSetAttribute(attn_sparsemax_kernel,
                         cudaFuncAttributeMaxDynamicSharedMemorySize, ATTN_SMEM_BYTES);

    // 1) QKV projections (HMMA 3xBF16)
    {
        dim3 grid(6, 128);
        mma_qkv<<<grid, 256>>>(x, Wq, bq, Wk, bk, Wv, bv, qkv);
    }

    // 2) scores + sparsemax + head average -> avg_attention (in d_out)
    attn_sparsemax_kernel<<<NROWS / 16, 512, ATTN_SMEM_BYTES>>>(qkv, avg);

    // 3) tmp[b] = avg[b] @ v[b]  (HMMA 3xBF16)
    {
        dim3 grid(2, 4, BB);
        mma_nn<<<grid, 256>>>(avg, qkv, tmp);
    }

    // 4) out = tmp @ Wo^T + bo  (HMMA 3xBF16)
    {
        dim3 grid(2, 128);
        mma_out<<<grid, 256>>>(tmp, Wo, bo, out);
    }
}

// round 9
// speedup vs baseline: 2.9554x; 1.1653x over previous
#include <cuda_runtime.h>
#include <cuda_bf16.h>
#include <cstdint>
#include <math.h>
#include <math_constants.h>

// Problem constants
#define BB 32
#define SS 512
#define DD 256
#define HH 8
#define DHH 32
#define NROWS (BB*SS)

// Scratch (__device__ globals; allocation is banned)
__device__ float g_qkv[(size_t)NROWS * 768];   // [row][0:256)=q, [256:512)=k, [512:768)=v
__device__ float g_tmp[(size_t)NROWS * 256];   // avg @ v result

// ---------------------------------------------------------------------------
// bf16 split + pack helpers (3xBF16 fp32 emulation)
// ---------------------------------------------------------------------------
__device__ __forceinline__ void splitpk(float x, float y, uint32_t& h, uint32_t& l) {
    __nv_bfloat16 hx = __float2bfloat16(x), hy = __float2bfloat16(y);
    float rx = x - __bfloat162float(hx);
    float ry = y - __bfloat162float(hy);
    __nv_bfloat16 lx = __float2bfloat16(rx), ly = __float2bfloat16(ry);
    h = (uint32_t)__bfloat16_as_ushort(hx) | ((uint32_t)__bfloat16_as_ushort(hy) << 16);
    l = (uint32_t)__bfloat16_as_ushort(lx) | ((uint32_t)__bfloat16_as_ushort(ly) << 16);
}

__device__ __forceinline__ uint32_t cvta_s(const void* p) {
    return (uint32_t)__cvta_generic_to_shared(p);
}

__device__ __forceinline__ void ldmx4(uint32_t r[4], uint32_t addr) {
    asm volatile("ldmatrix.sync.aligned.m8n8.x4.shared.b16 {%0,%1,%2,%3}, [%4];"
                 : "=r"(r[0]), "=r"(r[1]), "=r"(r[2]), "=r"(r[3]) : "r"(addr));
}
__device__ __forceinline__ void ldmx4t(uint32_t r[4], uint32_t addr) {
    asm volatile("ldmatrix.sync.aligned.m8n8.x4.trans.shared.b16 {%0,%1,%2,%3}, [%4];"
                 : "=r"(r[0]), "=r"(r[1]), "=r"(r[2]), "=r"(r[3]) : "r"(addr));
}

__device__ __forceinline__ void mma16816(float c[4], const uint32_t a[4],
                                         uint32_t b0, uint32_t b1) {
    asm volatile(
        "mma.sync.aligned.m16n8k16.row.col.f32.bf16.bf16.f32 "
        "{%0,%1,%2,%3}, {%4,%5,%6,%7}, {%8,%9}, {%0,%1,%2,%3};"
        : "+f"(c[0]), "+f"(c[1]), "+f"(c[2]), "+f"(c[3])
        : "r"(a[0]), "r"(a[1]), "r"(a[2]), "r"(a[3]), "r"(b0), "r"(b1));
}

// ---------------------------------------------------------------------------
// Tile strides (bf16 elements per row, padded for conflict-free ldmatrix)
// ---------------------------------------------------------------------------
#define AT_STR 40    // K-major tiles: 32 k + 8 pad
#define BN_STR 136   // NN B tile [k][n]: 128 n + 8 pad

// Stage a 128x32 fp32 K-contig tile -> hi/lo bf16 smem (row stride AT_STR)
__device__ __forceinline__ void stage_tn(uint16_t* hi, uint16_t* lo,
                                         const float4 f[4], int tid) {
    int row = tid >> 1, kh = (tid & 1) * 16;
    uint4 H0, H1, L0, L1;
    splitpk(f[0].x, f[0].y, H0.x, L0.x); splitpk(f[0].z, f[0].w, H0.y, L0.y);
    splitpk(f[1].x, f[1].y, H0.z, L0.z); splitpk(f[1].z, f[1].w, H0.w, L0.w);
    splitpk(f[2].x, f[2].y, H1.x, L1.x); splitpk(f[2].z, f[2].w, H1.y, L1.y);
    splitpk(f[3].x, f[3].y, H1.z, L1.z); splitpk(f[3].z, f[3].w, H1.w, L1.w);
    *(uint4*)(hi + row * AT_STR + kh)     = H0;
    *(uint4*)(hi + row * AT_STR + kh + 8) = H1;
    *(uint4*)(lo + row * AT_STR + kh)     = L0;
    *(uint4*)(lo + row * AT_STR + kh + 8) = L1;
}

// Stage a 32x128 fp32 N-contig tile -> hi/lo bf16 smem [k][n] (stride BN_STR)
__device__ __forceinline__ void stage_nn_b(uint16_t* hi, uint16_t* lo,
                                           const float4 f[4], int tid) {
    int k = tid >> 3, nq = (tid & 7) * 16;
    uint4 H0, H1, L0, L1;
    splitpk(f[0].x, f[0].y, H0.x, L0.x); splitpk(f[0].z, f[0].w, H0.y, L0.y);
    splitpk(f[1].x, f[1].y, H0.z, L0.z); splitpk(f[1].z, f[1].w, H0.w, L0.w);
    splitpk(f[2].x, f[2].y, H1.x, L1.x); splitpk(f[2].z, f[2].w, H1.y, L1.y);
    splitpk(f[3].x, f[3].y, H1.z, L1.z); splitpk(f[3].z, f[3].w, H1.w, L1.w);
    *(uint4*)(hi + k * BN_STR + nq)     = H0;
    *(uint4*)(hi + k * BN_STR + nq + 8) = H1;
    *(uint4*)(lo + k * BN_STR + nq)     = L0;
    *(uint4*)(lo + k * BN_STR + nq + 8) = L1;
}

template<bool TRANSB>
__device__ __forceinline__ void compute_chunk(
    float c[4][4][4],
    const uint16_t* sAhi, const uint16_t* sAlo,
    const uint16_t* sBhi, const uint16_t* sBlo,
    int lane, int mrow0, int ncol0)
{
    const int lr = lane & 7, lg = lane >> 3;
#pragma unroll
    for (int k16 = 0; k16 < 32; k16 += 16) {
        uint32_t ah[4][4], al[4][4];
        uint32_t aoff = (uint32_t)(((mrow0 + (lane & 15)) * AT_STR + k16 + ((lane >> 4) << 3)) * 2);
#pragma unroll
        for (int mi = 0; mi < 4; ++mi) {
            ldmx4(ah[mi], cvta_s(sAhi) + aoff + mi * (16 * AT_STR * 2));
            ldmx4(al[mi], cvta_s(sAlo) + aoff + mi * (16 * AT_STR * 2));
        }
        uint32_t bh[2][4], bl[2][4];
#pragma unroll
        for (int nb = 0; nb < 2; ++nb) {
            uint32_t boff;
            if (TRANSB) {
                boff = (uint32_t)(((k16 + lr + ((lg & 1) << 3)) * BN_STR
                                   + ncol0 + nb * 16 + ((lg & 2) << 2)) * 2);
                ldmx4t(bh[nb], cvta_s(sBhi) + boff);
                ldmx4t(bl[nb], cvta_s(sBlo) + boff);
            } else {
                boff = (uint32_t)(((ncol0 + nb * 16 + lr + ((lg & 2) << 2)) * AT_STR
                                   + k16 + ((lg & 1) << 3)) * 2);
                ldmx4(bh[nb], cvta_s(sBhi) + boff);
                ldmx4(bl[nb], cvta_s(sBlo) + boff);
            }
        }
#pragma unroll
        for (int mi = 0; mi < 4; ++mi)
#pragma unroll
            for (int nb = 0; nb < 2; ++nb)
#pragma unroll
                for (int half = 0; half < 2; ++half) {
                    float* cc = c[mi][nb * 2 + half];
                    mma16816(cc, ah[mi], bh[nb][half * 2], bh[nb][half * 2 + 1]);
                    mma16816(cc, ah[mi], bl[nb][half * 2], bl[nb][half * 2 + 1]);
                    mma16816(cc, al[mi], bh[nb][half * 2], bh[nb][half * 2 + 1]);
                }
    }
}

__device__ __forceinline__ void epilogue_store(
    float c[4][4][4], float* __restrict__ C, const float* __restrict__ bias,
    int ldc, int m0, int cn0, int mrow0, int ncol0, int lane)
{
#pragma unroll
    for (int mi = 0; mi < 4; ++mi) {
        int r = m0 + mrow0 + mi * 16 + (lane >> 2);
#pragma unroll
        for (int ni = 0; ni < 4; ++ni) {
            int cl = ncol0 + ni * 8 + ((lane & 3) << 1);
            float b0 = 0.f, b1 = 0.f;
            if (bias) { b0 = bias[cl]; b1 = bias[cl + 1]; }
            float2 v0 = make_float2(c[mi][ni][0] + b0, c[mi][ni][1] + b1);
            float2 v1 = make_float2(c[mi][ni][2] + b0, c[mi][ni][3] + b1);
            *(float2*)(C + (size_t)r * ldc + cn0 + cl) = v0;
            *(float2*)(C + (size_t)(r + 8) * ldc + cn0 + cl) = v1;
        }
    }
}

// ---------------------------------------------------------------------------
// TN GEMM body (unchanged from R8)
// ---------------------------------------------------------------------------
__device__ __forceinline__ void gemm_tn_mma_body(
    const float* __restrict__ A, const float* __restrict__ B,
    const float* __restrict__ bias, float* __restrict__ C,
    int K, int lda, int ldb, int ldc, int m0, int cn0)
{
    __shared__ __align__(16) uint16_t sAhi[128 * AT_STR];
    __shared__ __align__(16) uint16_t sAlo[128 * AT_STR];
    __shared__ __align__(16) uint16_t sBhi[128 * AT_STR];
    __shared__ __align__(16) uint16_t sBlo[128 * AT_STR];

    const int tid = threadIdx.x;
    const int lane = tid & 31, warp = tid >> 5;
    const int mrow0 = (warp & 1) * 64, ncol0 = (warp >> 1) * 32;
    const int row = tid >> 1, kh = (tid & 1) * 16;

    float c[4][4][4];
#pragma unroll
    for (int i = 0; i < 4; ++i)
#pragma unroll
        for (int j = 0; j < 4; ++j)
#pragma unroll
            for (int q = 0; q < 4; ++q) c[i][j][q] = 0.f;

    const float* pA = A + (size_t)(m0 + row) * lda + kh;
    const float* pB = B + (size_t)row * ldb + kh;

    float4 fa[4], fb[4];
#pragma unroll
    for (int i = 0; i < 4; ++i) {
        fa[i] = *(const float4*)(pA + i * 4);
        fb[i] = *(const float4*)(pB + i * 4);
    }

    for (int k0 = 0; k0 < K; k0 += 32) {
        stage_tn(sAhi, sAlo, fa, tid);
        stage_tn(sBhi, sBlo, fb, tid);
        __syncthreads();
        if (k0 + 32 < K) {
#pragma unroll
            for (int i = 0; i < 4; ++i) {
                fa[i] = *(const float4*)(pA + k0 + 32 + i * 4);
                fb[i] = *(const float4*)(pB + k0 + 32 + i * 4);
            }
        }
        compute_chunk<false>(c, sAhi, sAlo, sBhi, sBlo, lane, mrow0, ncol0);
        __syncthreads();
    }
    epilogue_store(c, C, bias, ldc, m0, cn0, mrow0, ncol0, lane);
}

__global__ __launch_bounds__(256) void mma_qkv(
    const float* __restrict__ x,
    const float* __restrict__ Wq, const float* __restrict__ bq,
    const float* __restrict__ Wk, const float* __restrict__ bk,
    const float* __restrict__ Wv, const float* __restrict__ bv,
    float* __restrict__ qkv)
{
    const int z = blockIdx.x;
    const int m0 = blockIdx.y * 128;
    const float* B; const float* bias;
    if (z < 2)      { B = Wq + (size_t)z * 128 * 256;       bias = bq + z * 128; }
    else if (z < 4) { B = Wk + (size_t)(z - 2) * 128 * 256; bias = bk + (z - 2) * 128; }
    else            { B = Wv + (size_t)(z - 4) * 128 * 256; bias = bv + (z - 4) * 128; }
    gemm_tn_mma_body(x, B, bias, qkv, 256, 256, 256, 768, m0, z * 128);
}

__global__ __launch_bounds__(256) void mma_out(
    const float* __restrict__ tmp, const float* __restrict__ Wo,
    const float* __restrict__ bo, float* __restrict__ out)
{
    const int n0 = blockIdx.x * 128;
    const int m0 = blockIdx.y * 128;
    gemm_tn_mma_body(tmp, Wo + (size_t)n0 * 256, bo + n0, out, 256, 256, 256, 256, m0, n0);
}

__global__ __launch_bounds__(256) void mma_nn(
    const float* __restrict__ avg, const float* __restrict__ qkv,
    float* __restrict__ tmp)
{
    __shared__ __align__(16) uint16_t sAhi[128 * AT_STR];
    __shared__ __align__(16) uint16_t sAlo[128 * AT_STR];
    __shared__ __align__(16) uint16_t sBhi[32 * BN_STR];
    __shared__ __align__(16) uint16_t sBlo[32 * BN_STR];

    const int tid = threadIdx.x;
    const int lane = tid & 31, warp = tid >> 5;
    const int mrow0 = (warp & 1) * 64, ncol0 = (warp >> 1) * 32;
    const int n0 = blockIdx.x * 128;
    const int m0 = blockIdx.y * 128;
    const int b  = blockIdx.z;

    const float* A = avg + (size_t)b * 512 * 512;
    const float* B = qkv + (size_t)b * 512 * 768 + 512;

    float c[4][4][4];
#pragma unroll
    for (int i = 0; i < 4; ++i)
#pragma unroll
        for (int j = 0; j < 4; ++j)
#pragma unroll
            for (int q = 0; q < 4; ++q) c[i][j][q] = 0.f;

    const int row = tid >> 1, kh = (tid & 1) * 16;
    const int bk = tid >> 3, bn = (tid & 7) * 16;
    const float* pA = A + (size_t)(m0 + row) * 512 + kh;
    const float* pB = B + n0 + bn;

    float4 fa[4], fb[4];
#pragma unroll
    for (int i = 0; i < 4; ++i) {
        fa[i] = *(const float4*)(pA + i * 4);
        fb[i] = *(const float4*)(pB + (size_t)bk * 768 + i * 4);
    }

    for (int k0 = 0; k0 < 512; k0 += 32) {
        stage_tn(sAhi, sAlo, fa, tid);
        stage_nn_b(sBhi, sBlo, fb, tid);
        __syncthreads();
        if (k0 + 32 < 512) {
#pragma unroll
            for (int i = 0; i < 4; ++i) {
                fa[i] = *(const float4*)(pA + k0 + 32 + i * 4);
                fb[i] = *(const float4*)(pB + (size_t)(k0 + 32 + bk) * 768 + i * 4);
            }
        }
        compute_chunk<true>(c, sAhi, sAlo, sBhi, sBlo, lane, mrow0, ncol0);
        __syncthreads();
    }
    epilogue_store(c, tmp, nullptr, 256, b * 512 + m0, n0, mrow0, ncol0, lane);
}

// ---------------------------------------------------------------------------
// Attention v3: score computation on tensor pipe (m16n8k16, 3xBF16 split),
// scores -> smem fp32 (stride 522, conflict-free), then warp sparsemax.
// Block: 512 threads (16 warps), 32 queries; loop 8 heads x 2 key-chunks(256).
// ---------------------------------------------------------------------------
#define SC_STR 522
#define AK_OFF   0
#define AKL_OFF  20480
#define AQ_OFF   40960
#define AQL_OFF  43520
#define ASC_OFF  46080
#define ATTN_SMEM_BYTES (46080 + 32 * SC_STR * 4)   // 46080 + 66816 = 112896

__global__ __launch_bounds__(512, 2) void attn_sparsemax_kernel(
    const float* __restrict__ qkv, float* __restrict__ avg)
{
    extern __shared__ __align__(16) char sm[];
    uint16_t* Khi = (uint16_t*)(sm + AK_OFF);    // [256][AT_STR]
    uint16_t* Klo = (uint16_t*)(sm + AKL_OFF);
    uint16_t* Qhi = (uint16_t*)(sm + AQ_OFF);    // [32][AT_STR]
    uint16_t* Qlo = (uint16_t*)(sm + AQL_OFF);
    float*    Ssc = (float*)(sm + ASC_OFF);      // [32][SC_STR]

    const int tid  = threadIdx.x;
    const int lane = tid & 31, w = tid >> 5;     // 16 warps
    const int b    = blockIdx.x >> 4;
    const int s0   = (blockIdx.x & 15) << 5;     // 32 queries per block

    const float* qbase = qkv + (size_t)b * 512 * 768;
    const float* kbase = qbase + 256;

    float acc[2][16];
#pragma unroll
    for (int qi = 0; qi < 2; ++qi)
#pragma unroll
        for (int i = 0; i < 16; ++i) acc[qi][i] = 0.f;

    const int lr = lane & 7, lg = lane >> 3;

    for (int h = 0; h < HH; ++h) {
        __syncthreads();   // protect Q/K/Ssc from previous head's readers

        // ---- stage Q (32 x 32) hi/lo ----
        {
            int r = tid >> 4, e2 = (tid & 15) * 2;
            const float* g = qbase + (size_t)(s0 + r) * 768 + h * 32 + e2;
            uint32_t hp, lp;
            splitpk(g[0], g[1], hp, lp);
            *(uint32_t*)(Qhi + r * AT_STR + e2) = hp;
            *(uint32_t*)(Qlo + r * AT_STR + e2) = lp;
        }

#pragma unroll
        for (int ck = 0; ck < 2; ++ck) {
            if (ck) __syncthreads();   // chunk0 MMA reads done before restage
            // ---- stage K chunk (256 x 32) hi/lo ----
            {
                int r = tid >> 1, kh = (tid & 1) * 16;
                const float* g = kbase + (size_t)(ck * 256 + r) * 768 + h * 32 + kh;
                float4 f[4];
#pragma unroll
                for (int i = 0; i < 4; ++i) f[i] = *(const float4*)(g + i * 4);
                uint4 H0, H1, L0, L1;
                splitpk(f[0].x, f[0].y, H0.x, L0.x); splitpk(f[0].z, f[0].w, H0.y, L0.y);
                splitpk(f[1].x, f[1].y, H0.z, L0.z); splitpk(f[1].z, f[1].w, H0.w, L0.w);
                splitpk(f[2].x, f[2].y, H1.x, L1.x); splitpk(f[2].z, f[2].w, H1.y, L1.y);
                splitpk(f[3].x, f[3].y, H1.z, L1.z); splitpk(f[3].z, f[3].w, H1.w, L1.w);
                *(uint4*)(Khi + r * AT_STR + kh)     = H0;
                *(uint4*)(Khi + r * AT_STR + kh + 8) = H1;
                *(uint4*)(Klo + r * AT_STR + kh)     = L0;
                *(uint4*)(Klo + r * AT_STR + kh + 8) = L1;
            }
            __syncthreads();

            // ---- score MMA: warp w -> 16 key-cols [w*16, w*16+16) of chunk ----
            float c[2][2][4];
#pragma unroll
            for (int mi = 0; mi < 2; ++mi)
#pragma unroll
                for (int hf = 0; hf < 2; ++hf)
#pragma unroll
                    for (int q = 0; q < 4; ++q) c[mi][hf][q] = 0.f;

#pragma unroll
            for (int k16 = 0; k16 < 32; k16 += 16) {
                uint32_t aoff = (uint32_t)(((lane & 15) * AT_STR + k16 + ((lane >> 4) << 3)) * 2);
                uint32_t ah[2][4], al[2][4];
#pragma unroll
                for (int mi = 0; mi < 2; ++mi) {
                    ldmx4(ah[mi], cvta_s(Qhi) + aoff + mi * (16 * AT_STR * 2));
                    ldmx4(al[mi], cvta_s(Qlo) + aoff + mi * (16 * AT_STR * 2));
                }
                uint32_t boff = (uint32_t)(((w * 16 + lr + ((lg & 2) << 2)) * AT_STR
                                            + k16 + ((lg & 1) << 3)) * 2);
                uint32_t bh[4], bl[4];
                ldmx4(bh, cvta_s(Khi) + boff);
                ldmx4(bl, cvta_s(Klo) + boff);
#pragma unroll
                for (int mi = 0; mi < 2; ++mi)
#pragma unroll
                    for (int hf = 0; hf < 2; ++hf) {
                        float* cc = c[mi][hf];
                        mma16816(cc, ah[mi], bh[hf * 2], bh[hf * 2 + 1]);
                        mma16816(cc, ah[mi], bl[hf * 2], bl[hf * 2 + 1]);
                        mma16816(cc, al[mi], bh[hf * 2], bh[hf * 2 + 1]);
                    }
            }

            // ---- scale + diagonal mask + store to Ssc ----
#pragma unroll
            for (int mi = 0; mi < 2; ++mi)
#pragma unroll
                for (int hf = 0; hf < 2; ++hf) {
                    int gc = ck * 256 + w * 16 + hf * 8 + ((lane & 3) << 1);
                    int r0 = mi * 16 + (lane >> 2);
                    int r1 = r0 + 8;
                    float v0 = c[mi][hf][0] * 0.17677669529663687f;
                    float v1 = c[mi][hf][1] * 0.17677669529663687f;
                    float v2 = c[mi][hf][2] * 0.17677669529663687f;
                    float v3 = c[mi][hf][3] * 0.17677669529663687f;
                    if (gc     == s0 + r0) v0 = -CUDART_INF_F;
                    if (gc + 1 == s0 + r0) v1 = -CUDART_INF_F;
                    if (gc     == s0 + r1) v2 = -CUDART_INF_F;
                    if (gc + 1 == s0 + r1) v3 = -CUDART_INF_F;
                    *(float2*)&Ssc[r0 * SC_STR + gc] = make_float2(v0, v1);
                    *(float2*)&Ssc[r1 * SC_STR + gc] = make_float2(v2, v3);
                }
        }
        __syncthreads();   // all scores visible

        // ---- exact sparsemax (Michelot): warp w -> queries w*2, w*2+1 ----
#pragma unroll
        for (int qi = 0; qi < 2; ++qi) {
            int q = w * 2 + qi;
            float zz[16];
#pragma unroll
            for (int i = 0; i < 16; ++i) zz[i] = Ssc[q * SC_STR + lane + 32 * i];

            float tau = -CUDART_INF_F;
            int prevc = -1;
            for (int it = 0; it < 64; ++it) {
                float sa = 0.f;
                int ca = 0;
#pragma unroll
                for (int i = 0; i < 16; ++i) {
                    if (zz[i] > tau) { sa += zz[i]; ca++; }
                }
#pragma unroll
                for (int o = 16; o; o >>= 1)
                    sa += __shfl_xor_sync(0xffffffffu, sa, o);
                ca = __reduce_add_sync(0xffffffffu, ca);
                if (ca == prevc || ca == 0) break;
                prevc = ca;
                tau = (sa - 1.0f) / (float)ca;
            }
#pragma unroll
            for (int i = 0; i < 16; ++i)
                acc[qi][i] += fmaxf(zz[i] - tau, 0.f) * 0.125f;
        }
    }

    // ---- write head-averaged rows ----
#pragma unroll
    for (int qi = 0; qi < 2; ++qi) {
        float* dst = avg + (size_t)(b * 512 + s0 + w * 2 + qi) * 512;
#pragma unroll
        for (int i = 0; i < 16; ++i) dst[lane + 32 * i] = acc[qi][i];
    }
}

// ---------------------------------------------------------------------------
extern "C" void kernel_launch(void* const* d_in, const int* in_sizes, int n_in,
                              void* d_out, int out_size)
{
    const float* x  = (const float*)d_in[0];
    const float* Wq = (const float*)d_in[1];
    const float* bq = (const float*)d_in[2];
    const float* Wk = (const float*)d_in[3];
    const float* bk = (const float*)d_in[4];
    const float* Wv = (const float*)d_in[5];
    const float* bv = (const float*)d_in[6];
    const float* Wo = (const float*)d_in[7];
    const float* bo = (const float*)d_in[8];

    float* out = (float*)d_out;                        // [32,512,256]
    float* avg = out + (size_t)NROWS * DD;             // [32,512,512]

    float* qkv = nullptr;
    float* tmp = nullptr;
    cudaGetSymbolAddress((void**)&qkv, g_qkv);
    cudaGetSymbolAddress((void**)&tmp, g_tmp);

    cudaFuncSetAttribute(attn_sparsemax_kernel,
                         cudaFuncAttributeMaxDynamicSharedMemorySize, ATTN_SMEM_BYTES);

    // 1) QKV projections (HMMA 3xBF16)
    {
        dim3 grid(6, 128);
        mma_qkv<<<grid, 256>>>(x, Wq, bq, Wk, bk, Wv, bv, qkv);
    }

    // 2) scores (HMMA) + sparsemax + head average -> avg_attention (in d_out)
    attn_sparsemax_kernel<<<NROWS / 32, 512, ATTN_SMEM_BYTES>>>(qkv, avg);

    // 3) tmp[b] = avg[b] @ v[b]  (HMMA 3xBF16)
    {
        dim3 grid(2, 4, BB);
        mma_nn<<<grid, 256>>>(avg, qkv, tmp);
    }

    // 4) out = tmp @ Wo^T + bo  (HMMA 3xBF16)
    {
        dim3 grid(2, 128);
        mma_out<<<grid, 256>>>(tmp, Wo, bo, out);
    }
}